// round 1
// baseline (speedup 1.0000x reference)
#include <cuda_runtime.h>

// Problem constants
#define B_    2
#define L_    2048
#define QD_   1024
#define H_    16
#define D_    64
#define INNER_ 1024           // H_*D_
#define M_    4096            // B_*L_

// Scratch (allocation-free rule: __device__ globals)
__device__ float g_Q[B_ * H_ * L_ * D_];
__device__ float g_K[B_ * H_ * L_ * D_];
__device__ float g_V[B_ * H_ * L_ * D_];
__device__ float g_O[M_ * INNER_];

// ---------------------------------------------------------------------------
// Kernel 1: fused QKV projection + per-head RMSNorm + RoPE
//   grid.x = M_/64 token tiles, grid.y = 48 output-head tiles
//   (0..15 -> Q heads, 16..31 -> K heads, 32..47 -> V heads)
// ---------------------------------------------------------------------------
__global__ __launch_bounds__(256) void qkv_kernel(
    const float* __restrict__ x, const float* __restrict__ pe,
    const float* __restrict__ Wq, const float* __restrict__ Wkv,
    const float* __restrict__ q_scale, const float* __restrict__ k_scale)
{
    __shared__ float As[16][64];   // [k][m]
    __shared__ float Bs[16][64];   // [k][n]
    __shared__ float S[64][65];    // [m][d] epilogue tile

    const int m0 = blockIdx.x * 64;
    const int region = blockIdx.y;
    int kind, h, wrow0;
    const float* W;
    if (region < 16)      { kind = 0; h = region;      W = Wq;  wrow0 = h * D_; }
    else if (region < 32) { kind = 1; h = region - 16; W = Wkv; wrow0 = h * D_; }
    else                  { kind = 2; h = region - 32; W = Wkv; wrow0 = INNER_ + h * D_; }

    const int t  = threadIdx.x;
    const int tx = t & 15, ty = t >> 4;
    const int lr  = t >> 2;          // 0..63
    const int lc4 = (t & 3) * 4;     // 0,4,8,12

    float acc[4][4] = {};
    for (int k0 = 0; k0 < QD_; k0 += 16) {
        float4 av = *reinterpret_cast<const float4*>(x + (size_t)(m0 + lr) * QD_ + k0 + lc4);
        float4 bv = *reinterpret_cast<const float4*>(W + (size_t)(wrow0 + lr) * QD_ + k0 + lc4);
        As[lc4 + 0][lr] = av.x; As[lc4 + 1][lr] = av.y;
        As[lc4 + 2][lr] = av.z; As[lc4 + 3][lr] = av.w;
        Bs[lc4 + 0][lr] = bv.x; Bs[lc4 + 1][lr] = bv.y;
        Bs[lc4 + 2][lr] = bv.z; Bs[lc4 + 3][lr] = bv.w;
        __syncthreads();
        #pragma unroll
        for (int kk = 0; kk < 16; ++kk) {
            float4 a4 = *reinterpret_cast<const float4*>(&As[kk][ty * 4]);
            float4 b4 = *reinterpret_cast<const float4*>(&Bs[kk][tx * 4]);
            float a[4] = {a4.x, a4.y, a4.z, a4.w};
            float b[4] = {b4.x, b4.y, b4.z, b4.w};
            #pragma unroll
            for (int i = 0; i < 4; ++i)
                #pragma unroll
                for (int j = 0; j < 4; ++j)
                    acc[i][j] = fmaf(a[i], b[j], acc[i][j]);
        }
        __syncthreads();
    }

    #pragma unroll
    for (int i = 0; i < 4; ++i)
        #pragma unroll
        for (int j = 0; j < 4; ++j)
            S[ty * 4 + i][tx * 4 + j] = acc[i][j];
    __syncthreads();

    const int row = t >> 2;          // 0..63 token within tile
    const int seg = t & 3;           // quarter of the 64-wide head row
    const int m = m0 + row;
    const int b = m / L_, l = m % L_;

    if (kind == 2) {                 // V: passthrough
        float* dst = g_V + ((size_t)(b * H_ + h) * L_ + l) * D_;
        #pragma unroll
        for (int c = seg * 16; c < seg * 16 + 16; ++c) dst[c] = S[row][c];
    } else {                         // Q/K: RMSNorm + scale + RoPE
        float ss = 0.f;
        #pragma unroll
        for (int c = seg * 16; c < seg * 16 + 16; ++c) {
            float v = S[row][c];
            ss = fmaf(v, v, ss);
        }
        ss += __shfl_xor_sync(0xffffffffu, ss, 1);
        ss += __shfl_xor_sync(0xffffffffu, ss, 2);
        const float rrms = rsqrtf(ss * (1.f / 64.f) + 1e-6f);
        const float* scale = (kind == 0) ? q_scale : k_scale;
        const float* pel = pe + (size_t)l * (D_ / 2) * 4;   // [32][2][2]
        float* dst = (kind == 0 ? g_Q : g_K) + ((size_t)(b * H_ + h) * L_ + l) * D_;
        #pragma unroll
        for (int c = seg * 16; c < seg * 16 + 16; c += 2) {
            float v0 = S[row][c]     * rrms * scale[c];
            float v1 = S[row][c + 1] * rrms * scale[c + 1];
            const float* p = pel + (c >> 1) * 4;
            dst[c]     = p[0] * v0 + p[1] * v1;
            dst[c + 1] = p[2] * v0 + p[3] * v1;
        }
    }
}

// ---------------------------------------------------------------------------
// Kernel 2: flash attention (fp32, online softmax)
//   grid.x = L_/64 q-tiles, grid.y = B_*H_
//   Smem: Qs[d][i] (Q transposed, pre-scaled by 1/sqrt(D)),
//         KP: K transposed [d][j] during S-compute, then reused for P[i][j],
//         Vs[j][d] natural. All [64][64] (48KB exactly), aligned LDS.128.
// ---------------------------------------------------------------------------
__global__ __launch_bounds__(256) void attn_kernel()
{
    __shared__ float Qs[64][64];
    __shared__ float KP[64][64];
    __shared__ float Vs[64][64];

    const int bh = blockIdx.y;
    const int q0 = blockIdx.x * 64;
    const float* Qg = g_Q + ((size_t)bh * L_ + q0) * D_;
    const float* Kg = g_K + (size_t)bh * L_ * D_;
    const float* Vg = g_V + (size_t)bh * L_ * D_;

    const int t = threadIdx.x;
    const int tx = t & 15, ty = t >> 4;

    // Q load, transposed, pre-scaled. Swizzled mapping (r = lin%64) makes the
    // column smem stores conflict-free (trades for uncoalesced-but-L2-cheap loads).
    #pragma unroll
    for (int it = 0; it < 4; ++it) {
        int lin = t + it * 256;
        int r  = lin & 63;
        int c4 = (lin >> 6) * 4;
        float4 v = *reinterpret_cast<const float4*>(Qg + (size_t)r * D_ + c4);
        Qs[c4 + 0][r] = v.x * 0.125f; Qs[c4 + 1][r] = v.y * 0.125f;
        Qs[c4 + 2][r] = v.z * 0.125f; Qs[c4 + 3][r] = v.w * 0.125f;
    }

    float m_run[4], l_run[4], o[4][4];
    #pragma unroll
    for (int i = 0; i < 4; ++i) {
        m_run[i] = -1e30f; l_run[i] = 0.f;
        #pragma unroll
        for (int d = 0; d < 4; ++d) o[i][d] = 0.f;
    }

    for (int kt = 0; kt < L_; kt += 64) {
        __syncthreads();   // prior PV done (and Q loads on first iter)
        // K transposed (swizzled mapping, conflict-free stores), V natural (coalesced)
        #pragma unroll
        for (int it = 0; it < 4; ++it) {
            int lin = t + it * 256;
            int rk  = lin & 63;
            int ck4 = (lin >> 6) * 4;
            float4 kv = *reinterpret_cast<const float4*>(Kg + (size_t)(kt + rk) * D_ + ck4);
            KP[ck4 + 0][rk] = kv.x; KP[ck4 + 1][rk] = kv.y;
            KP[ck4 + 2][rk] = kv.z; KP[ck4 + 3][rk] = kv.w;
            int rv  = lin >> 4;
            int cv4 = (lin & 15) * 4;
            float4 vv = *reinterpret_cast<const float4*>(Vg + (size_t)(kt + rv) * D_ + cv4);
            *reinterpret_cast<float4*>(&Vs[rv][cv4]) = vv;
        }
        __syncthreads();

        // S = (Q * 1/sqrt(D)) @ K^T, tile 64x64, reduce over d
        float s[4][4] = {};
        #pragma unroll
        for (int kk = 0; kk < 64; ++kk) {
            float4 a4 = *reinterpret_cast<const float4*>(&Qs[kk][ty * 4]);
            float4 b4 = *reinterpret_cast<const float4*>(&KP[kk][tx * 4]);
            float a[4] = {a4.x, a4.y, a4.z, a4.w};
            float b[4] = {b4.x, b4.y, b4.z, b4.w};
            #pragma unroll
            for (int i = 0; i < 4; ++i)
                #pragma unroll
                for (int j = 0; j < 4; ++j)
                    s[i][j] = fmaf(a[i], b[j], s[i][j]);
        }
        __syncthreads();   // everyone done reading K before KP is reused for P

        // Online softmax; row groups = 16 lanes sharing ty (shuffle-reduce)
        #pragma unroll
        for (int i = 0; i < 4; ++i) {
            float mx = fmaxf(fmaxf(s[i][0], s[i][1]), fmaxf(s[i][2], s[i][3]));
            #pragma unroll
            for (int off = 8; off; off >>= 1)
                mx = fmaxf(mx, __shfl_xor_sync(0xffffffffu, mx, off));
            float m_new = fmaxf(m_run[i], mx);
            float corr = __expf(m_run[i] - m_new);
            float p0 = __expf(s[i][0] - m_new);
            float p1 = __expf(s[i][1] - m_new);
            float p2 = __expf(s[i][2] - m_new);
            float p3 = __expf(s[i][3] - m_new);
            float rs = (p0 + p1) + (p2 + p3);
            #pragma unroll
            for (int off = 8; off; off >>= 1)
                rs += __shfl_xor_sync(0xffffffffu, rs, off);
            l_run[i] = l_run[i] * corr + rs;
            m_run[i] = m_new;
            #pragma unroll
            for (int d = 0; d < 4; ++d) o[i][d] *= corr;
            *reinterpret_cast<float4*>(&KP[ty * 4 + i][tx * 4]) = make_float4(p0, p1, p2, p3);
        }
        __syncthreads();

        // O += P @ V (reduce over j); P read column-wise (2 addr/warp broadcast)
        #pragma unroll
        for (int kk = 0; kk < 64; ++kk) {
            float a[4];
            #pragma unroll
            for (int i = 0; i < 4; ++i) a[i] = KP[ty * 4 + i][kk];
            float4 b4 = *reinterpret_cast<const float4*>(&Vs[kk][tx * 4]);
            float b[4] = {b4.x, b4.y, b4.z, b4.w};
            #pragma unroll
            for (int i = 0; i < 4; ++i)
                #pragma unroll
                for (int d = 0; d < 4; ++d)
                    o[i][d] = fmaf(a[i], b[d], o[i][d]);
        }
    }

    const int b = bh / H_, h = bh % H_;
    #pragma unroll
    for (int i = 0; i < 4; ++i) {
        float inv = 1.f / l_run[i];
        int l = q0 + ty * 4 + i;
        float* dst = g_O + (((size_t)b * L_ + l) * H_ + h) * D_ + tx * 4;
        #pragma unroll
        for (int d = 0; d < 4; ++d) dst[d] = o[i][d] * inv;
    }
}

// ---------------------------------------------------------------------------
// Kernel 3: output projection  out = g_O @ Wproj^T + bproj
// ---------------------------------------------------------------------------
__global__ __launch_bounds__(256) void proj_kernel(
    const float* __restrict__ Wproj, const float* __restrict__ bproj,
    float* __restrict__ out)
{
    __shared__ float As[16][64];
    __shared__ float Bs[16][64];

    const int m0 = blockIdx.x * 64;
    const int n0 = blockIdx.y * 64;
    const int t = threadIdx.x;
    const int tx = t & 15, ty = t >> 4;
    const int lr = t >> 2, lc4 = (t & 3) * 4;

    float acc[4][4] = {};
    for (int k0 = 0; k0 < INNER_; k0 += 16) {
        float4 av = *reinterpret_cast<const float4*>(g_O + (size_t)(m0 + lr) * INNER_ + k0 + lc4);
        float4 bv = *reinterpret_cast<const float4*>(Wproj + (size_t)(n0 + lr) * INNER_ + k0 + lc4);
        As[lc4 + 0][lr] = av.x; As[lc4 + 1][lr] = av.y;
        As[lc4 + 2][lr] = av.z; As[lc4 + 3][lr] = av.w;
        Bs[lc4 + 0][lr] = bv.x; Bs[lc4 + 1][lr] = bv.y;
        Bs[lc4 + 2][lr] = bv.z; Bs[lc4 + 3][lr] = bv.w;
        __syncthreads();
        #pragma unroll
        for (int kk = 0; kk < 16; ++kk) {
            float4 a4 = *reinterpret_cast<const float4*>(&As[kk][ty * 4]);
            float4 b4 = *reinterpret_cast<const float4*>(&Bs[kk][tx * 4]);
            float a[4] = {a4.x, a4.y, a4.z, a4.w};
            float b[4] = {b4.x, b4.y, b4.z, b4.w};
            #pragma unroll
            for (int i = 0; i < 4; ++i)
                #pragma unroll
                for (int j = 0; j < 4; ++j)
                    acc[i][j] = fmaf(a[i], b[j], acc[i][j]);
        }
        __syncthreads();
    }

    #pragma unroll
    for (int i = 0; i < 4; ++i) {
        int mI = m0 + ty * 4 + i;
        #pragma unroll
        for (int j = 0; j < 4; ++j) {
            int n = n0 + tx * 4 + j;
            out[(size_t)mI * QD_ + n] = acc[i][j] + bproj[n];
        }
    }
}

// ---------------------------------------------------------------------------
extern "C" void kernel_launch(void* const* d_in, const int* in_sizes, int n_in,
                              void* d_out, int out_size)
{
    const float* x   = (const float*)d_in[0];
    const float* pe  = (const float*)d_in[1];
    const float* Wq  = (const float*)d_in[2];
    const float* Wkv = (const float*)d_in[3];
    const float* Wp  = (const float*)d_in[4];
    const float* bp  = (const float*)d_in[5];
    const float* qs  = (const float*)d_in[6];
    const float* ks  = (const float*)d_in[7];
    float* out = (float*)d_out;

    qkv_kernel<<<dim3(M_ / 64, 48), 256>>>(x, pe, Wq, Wkv, qs, ks);
    attn_kernel<<<dim3(L_ / 64, B_ * H_), 256>>>();
    proj_kernel<<<dim3(M_ / 64, QD_ / 64), 256>>>(Wp, bp, out);
}

// round 3
// speedup vs baseline: 3.7775x; 3.7775x over previous
#include <cuda_runtime.h>
#include <cuda_bf16.h>
#include <cstdint>

#define B_     2
#define L_     2048
#define QD_    1024
#define H_     16
#define D_     64
#define INNER_ 1024
#define M_     4096
#define NF_    3072

typedef __nv_bfloat16 bf16;

// ---------------------------------------------------------------------------
// Scratch (__device__ globals; allocation-free rule)
// ---------------------------------------------------------------------------
__device__ bf16 g_xh[M_ * QD_],  g_xl[M_ * QD_];
__device__ bf16 g_Wh[NF_ * QD_], g_Wl[NF_ * QD_];     // [Wq ; Wkv] fused rows
__device__ bf16 g_Ph[QD_ * INNER_], g_Pl[QD_ * INNER_];
__device__ bf16 g_Qh[M_ * INNER_], g_Ql[M_ * INNER_]; // [b*H+h][l][d]
__device__ bf16 g_Kh[M_ * INNER_], g_Kl[M_ * INNER_];
__device__ bf16 g_Vh[M_ * INNER_], g_Vl[M_ * INNER_];
__device__ bf16 g_Oh[M_ * INNER_], g_Ol[M_ * INNER_]; // [m][h*64+d]

// ---------------------------------------------------------------------------
// Baseline-PTX helpers (legal on .target sm_103 without 'a')
// ---------------------------------------------------------------------------
__device__ __forceinline__ uint32_t smem_u32(const void* p) {
    uint32_t a;
    asm("{ .reg .u64 t; cvta.to.shared.u64 t, %1; cvt.u32.u64 %0, t; }"
        : "=r"(a) : "l"(p));
    return a;
}
__device__ __forceinline__ void cpa16(uint32_t s, const void* g) {
    asm volatile("cp.async.cg.shared.global [%0], [%1], 16;" :: "r"(s), "l"(g));
}
#define CP_COMMIT() asm volatile("cp.async.commit_group;" ::: "memory")
#define CP_WAIT(n)  asm volatile("cp.async.wait_group %0;" :: "n"(n) : "memory")

__device__ __forceinline__ void ldx4(uint32_t r[4], uint32_t a) {
    asm volatile("ldmatrix.sync.aligned.m8n8.x4.shared.b16 {%0,%1,%2,%3}, [%4];"
        : "=r"(r[0]), "=r"(r[1]), "=r"(r[2]), "=r"(r[3]) : "r"(a));
}
__device__ __forceinline__ void ldx4t(uint32_t r[4], uint32_t a) {
    asm volatile("ldmatrix.sync.aligned.m8n8.x4.trans.shared.b16 {%0,%1,%2,%3}, [%4];"
        : "=r"(r[0]), "=r"(r[1]), "=r"(r[2]), "=r"(r[3]) : "r"(a));
}
__device__ __forceinline__ void mma16816(float c[4], const uint32_t a[4],
                                         const uint32_t b[2]) {
    asm volatile(
        "mma.sync.aligned.m16n8k16.row.col.f32.bf16.bf16.f32 "
        "{%0,%1,%2,%3}, {%4,%5,%6,%7}, {%8,%9}, {%0,%1,%2,%3};"
        : "+f"(c[0]), "+f"(c[1]), "+f"(c[2]), "+f"(c[3])
        : "r"(a[0]), "r"(a[1]), "r"(a[2]), "r"(a[3]), "r"(b[0]), "r"(b[1]));
}
__device__ __forceinline__ uint32_t swz(uint32_t o) { return o ^ ((o >> 3) & 0x70); }

__device__ __forceinline__ uint32_t packf2(float x, float y) {
    __nv_bfloat162 h = __float22bfloat162_rn(make_float2(x, y));
    return reinterpret_cast<uint32_t&>(h);
}
// split v0,v1 into hi/lo bf16 pairs and store as u32 to hi/lo arrays
__device__ __forceinline__ void store_hl(bf16* dh, bf16* dl, size_t idx,
                                         float v0, float v1) {
    bf16 h0 = __float2bfloat16(v0), h1 = __float2bfloat16(v1);
    float l0 = v0 - __bfloat162float(h0), l1 = v1 - __bfloat162float(h1);
    __nv_bfloat162 hh = __halves2bfloat162(h0, h1);
    *reinterpret_cast<uint32_t*>(dh + idx) = reinterpret_cast<uint32_t&>(hh);
    *reinterpret_cast<uint32_t*>(dl + idx) = packf2(l0, l1);
}

// ---------------------------------------------------------------------------
// fp32 -> bf16 hi/lo split
// ---------------------------------------------------------------------------
__global__ __launch_bounds__(256) void split_kernel(
    const float* __restrict__ s, bf16* __restrict__ hi, bf16* __restrict__ lo, int n4)
{
    int i = blockIdx.x * 256 + threadIdx.x;
    if (i >= n4) return;
    float4 v = reinterpret_cast<const float4*>(s)[i];
    store_hl(hi, lo, (size_t)i * 4,     v.x, v.y);
    store_hl(hi, lo, (size_t)i * 4 + 2, v.z, v.w);
}

// ---------------------------------------------------------------------------
// Shared HMMA GEMM mainloop: C[128m x 128n] = A[m][1024] * B[n][1024]^T
// bf16x3 (Ah*Bh + Ah*Bl + Al*Bh), fp32 accum in registers.
// 8 warps: wm = wid&3 (32-row strips), wn = wid>>2 (64-col strips).
// ---------------------------------------------------------------------------
#define GSTAGE 65536   // Ah 16K | Al 16K | Bh 16K | Bl 16K

__device__ __forceinline__ void gemm_main(
    const bf16* __restrict__ Ah, const bf16* __restrict__ Al,
    const bf16* __restrict__ Bh, const bf16* __restrict__ Bl,
    int m0, int n0, char* smem, float c[2][8][4])
{
    const int tid = threadIdx.x;
    const int lane = tid & 31, wid = tid >> 5;
    const int wm = wid & 3, wn = wid >> 2;
    const uint32_t sb = smem_u32(smem);

    const int arow = (lane & 7) + ((lane >> 3) & 1) * 8;   // A-frag lane row
    const int acb  = (lane >> 4) * 16;                     // A-frag lane col byte
    const int brow = (lane & 7) + ((lane >> 4) & 1) * 8;   // B-frag lane row
    const int bcb  = ((lane >> 3) & 1) * 16;               // B-frag lane col byte

    const bf16* srcs[4] = { Ah + (size_t)m0 * QD_, Al + (size_t)m0 * QD_,
                            Bh + (size_t)n0 * QD_, Bl + (size_t)n0 * QD_ };

    auto load_stage = [&](int st, int ch) {
        uint32_t base = sb + st * GSTAGE;
        #pragma unroll
        for (int mtx = 0; mtx < 4; ++mtx)
            #pragma unroll
            for (int i = 0; i < 4; ++i) {
                int u = tid + i * 256;
                int row = u >> 3, s7 = u & 7;
                cpa16(base + mtx * 16384 + swz(row * 128 + s7 * 16),
                      srcs[mtx] + (size_t)row * QD_ + ch * 64 + s7 * 8);
            }
    };

    load_stage(0, 0);
    CP_COMMIT();

    for (int ch = 0; ch < 16; ++ch) {
        if (ch < 15) {
            load_stage((ch + 1) & 1, ch + 1);
            CP_COMMIT();
            CP_WAIT(1);
        } else {
            CP_WAIT(0);
        }
        __syncthreads();

        uint32_t base = sb + (ch & 1) * GSTAGE;
        #pragma unroll
        for (int ks = 0; ks < 4; ++ks) {
            uint32_t ah[2][4], al[2][4];
            #pragma unroll
            for (int mi = 0; mi < 2; ++mi) {
                uint32_t ad = base + swz((wm * 32 + mi * 16 + arow) * 128 + ks * 32 + acb);
                ldx4(ah[mi], ad);
                ldx4(al[mi], ad + 16384);
            }
            uint32_t bhf[8][2], blf[8][2];
            #pragma unroll
            for (int ng = 0; ng < 4; ++ng) {
                uint32_t bd = base + 32768
                            + swz((wn * 64 + ng * 16 + brow) * 128 + ks * 32 + bcb);
                uint32_t r[4];
                ldx4(r, bd);
                bhf[2*ng][0]=r[0]; bhf[2*ng][1]=r[1]; bhf[2*ng+1][0]=r[2]; bhf[2*ng+1][1]=r[3];
                ldx4(r, bd + 16384);
                blf[2*ng][0]=r[0]; blf[2*ng][1]=r[1]; blf[2*ng+1][0]=r[2]; blf[2*ng+1][1]=r[3];
            }
            #pragma unroll
            for (int mi = 0; mi < 2; ++mi)
                #pragma unroll
                for (int ni = 0; ni < 8; ++ni) {
                    mma16816(c[mi][ni], ah[mi], bhf[ni]);
                    mma16816(c[mi][ni], ah[mi], blf[ni]);
                    mma16816(c[mi][ni], al[mi], bhf[ni]);
                }
        }
        __syncthreads();
    }
}

// ---------------------------------------------------------------------------
// QKV projection GEMM + RMSNorm + RoPE, writes Q/K/V bf16 hi/lo
//   grid = (M_/128, NF_/128), 256 threads
// ---------------------------------------------------------------------------
__global__ __launch_bounds__(256, 1) void qkv_mma(
    const float* __restrict__ pe,
    const float* __restrict__ qsc, const float* __restrict__ ksc)
{
    extern __shared__ char smem[];
    const int m0 = blockIdx.x * 128, n0 = blockIdx.y * 128;
    float c[2][8][4];
    #pragma unroll
    for (int i = 0; i < 2; ++i)
        #pragma unroll
        for (int j = 0; j < 8; ++j)
            #pragma unroll
            for (int k = 0; k < 4; ++k) c[i][j][k] = 0.f;

    gemm_main(g_xh, g_xl, g_Wh, g_Wl, m0, n0, smem, c);

    const int tid = threadIdx.x, lane = tid & 31, wid = tid >> 5;
    const int wm = wid & 3, wn = wid >> 2;
    const int tq = lane & 3, g = lane >> 2;

    const int f0 = n0 + wn * 64;             // head-aligned (64) feature base
    const int kind = f0 >> 10;               // 0:Q 1:K 2:V
    const int h = (f0 & 1023) >> 6;
    bf16* dh = (kind == 0) ? g_Qh : (kind == 1) ? g_Kh : g_Vh;
    bf16* dl = (kind == 0) ? g_Ql : (kind == 1) ? g_Kl : g_Vl;
    const float* sc = (kind == 0) ? qsc : ksc;
    const float qm = (kind == 0) ? 0.125f : 1.f;   // fold 1/sqrt(D) into Q

    #pragma unroll
    for (int mi = 0; mi < 2; ++mi)
        #pragma unroll
        for (int half = 0; half < 2; ++half) {
            const int m = m0 + wm * 32 + mi * 16 + g + half * 8;
            const int b = m >> 11, l = m & 2047;
            const size_t obase = ((size_t)(b * H_ + h) * L_ + l) * 64;

            if (kind == 2) {
                #pragma unroll
                for (int ni = 0; ni < 8; ++ni) {
                    int d0 = ni * 8 + tq * 2;
                    store_hl(dh, dl, obase + d0,
                             c[mi][ni][half * 2], c[mi][ni][half * 2 + 1]);
                }
            } else {
                float ss = 0.f;
                #pragma unroll
                for (int ni = 0; ni < 8; ++ni) {
                    float v0 = c[mi][ni][half * 2], v1 = c[mi][ni][half * 2 + 1];
                    ss = fmaf(v0, v0, fmaf(v1, v1, ss));
                }
                ss += __shfl_xor_sync(0xffffffffu, ss, 1);
                ss += __shfl_xor_sync(0xffffffffu, ss, 2);
                const float rr = rsqrtf(ss * (1.f / 64.f) + 1e-6f);
                const float* pel = pe + (size_t)l * 128;
                #pragma unroll
                for (int ni = 0; ni < 8; ++ni) {
                    int d0 = ni * 8 + tq * 2;
                    float v0 = c[mi][ni][half * 2]     * rr * sc[d0];
                    float v1 = c[mi][ni][half * 2 + 1] * rr * sc[d0 + 1];
                    float4 p = *reinterpret_cast<const float4*>(pel + (d0 >> 1) * 4);
                    float o0 = (p.x * v0 + p.y * v1) * qm;
                    float o1 = (p.z * v0 + p.w * v1) * qm;
                    store_hl(dh, dl, obase + d0, o0, o1);
                }
            }
        }
}

// ---------------------------------------------------------------------------
// Output projection GEMM + bias -> fp32 out
//   grid = (M_/128, QD_/128), 256 threads
// ---------------------------------------------------------------------------
__global__ __launch_bounds__(256, 1) void proj_mma(
    const float* __restrict__ bp, float* __restrict__ out)
{
    extern __shared__ char smem[];
    const int m0 = blockIdx.x * 128, n0 = blockIdx.y * 128;
    float c[2][8][4];
    #pragma unroll
    for (int i = 0; i < 2; ++i)
        #pragma unroll
        for (int j = 0; j < 8; ++j)
            #pragma unroll
            for (int k = 0; k < 4; ++k) c[i][j][k] = 0.f;

    gemm_main(g_Oh, g_Ol, g_Ph, g_Pl, m0, n0, smem, c);

    const int tid = threadIdx.x, lane = tid & 31, wid = tid >> 5;
    const int wm = wid & 3, wn = wid >> 2;
    const int tq = lane & 3, g = lane >> 2;

    #pragma unroll
    for (int mi = 0; mi < 2; ++mi)
        #pragma unroll
        for (int half = 0; half < 2; ++half) {
            const int m = m0 + wm * 32 + mi * 16 + g + half * 8;
            #pragma unroll
            for (int ni = 0; ni < 8; ++ni) {
                int col = n0 + wn * 64 + ni * 8 + tq * 2;
                float2 bv = *reinterpret_cast<const float2*>(bp + col);
                float2 o = make_float2(c[mi][ni][half * 2]     + bv.x,
                                       c[mi][ni][half * 2 + 1] + bv.y);
                *reinterpret_cast<float2*>(out + (size_t)m * QD_ + col) = o;
            }
        }
}

// ---------------------------------------------------------------------------
// Flash attention, HMMA bf16x3, online softmax (FA2 layout)
//   grid = (L_/128, B_*H_), 256 threads (8 warps x 16 q-rows)
//   smem: Qh 16K | Ql 16K | 2 stages x (Kh 8K | Kl 8K | Vh 8K | Vl 8K)
// ---------------------------------------------------------------------------
#define ASTAGE 32768
#define ASMEM  (32768 + 2 * ASTAGE)

__global__ __launch_bounds__(256, 1) void attn_mma()
{
    extern __shared__ char smem[];
    const int tid = threadIdx.x, lane = tid & 31, w = tid >> 5;
    const int by = blockIdx.y;
    const int q0 = blockIdx.x * 128;
    const uint32_t sb = smem_u32(smem);

    const bf16* Qhp = g_Qh + ((size_t)by * L_ + q0) * 64;
    const bf16* Qlp = g_Ql + ((size_t)by * L_ + q0) * 64;
    const bf16* Khp = g_Kh + (size_t)by * L_ * 64;
    const bf16* Klp = g_Kl + (size_t)by * L_ * 64;
    const bf16* Vhp = g_Vh + (size_t)by * L_ * 64;
    const bf16* Vlp = g_Vl + (size_t)by * L_ * 64;

    const int tq = lane & 3, g = lane >> 2;
    const int arow = (lane & 7) + ((lane >> 3) & 1) * 8;
    const int acb  = (lane >> 4) * 16;
    const int brow = (lane & 7) + ((lane >> 4) & 1) * 8;
    const int bcb  = ((lane >> 3) & 1) * 16;

    auto load_kv = [&](int st, int kt) {
        uint32_t base = sb + 32768 + st * ASTAGE;
        const bf16* srcs[4] = { Khp, Klp, Vhp, Vlp };
        #pragma unroll
        for (int mtx = 0; mtx < 4; ++mtx)
            #pragma unroll
            for (int i = 0; i < 2; ++i) {
                int u = tid + i * 256;
                int row = u >> 3, s7 = u & 7;
                cpa16(base + mtx * 8192 + swz(row * 128 + s7 * 16),
                      srcs[mtx] + (size_t)(kt * 64 + row) * 64 + s7 * 8);
            }
    };

    // Q tiles (group 0) + stage 0
    #pragma unroll
    for (int i = 0; i < 4; ++i) {
        int u = tid + i * 256;
        int row = u >> 3, s7 = u & 7;
        cpa16(sb +         swz(row * 128 + s7 * 16), Qhp + (size_t)row * 64 + s7 * 8);
        cpa16(sb + 16384 + swz(row * 128 + s7 * 16), Qlp + (size_t)row * 64 + s7 * 8);
    }
    load_kv(0, 0);
    CP_COMMIT();

    float o[8][4];
    #pragma unroll
    for (int i = 0; i < 8; ++i)
        #pragma unroll
        for (int j = 0; j < 4; ++j) o[i][j] = 0.f;
    float mr0 = -1e30f, mr1 = -1e30f, lr0 = 0.f, lr1 = 0.f;
    uint32_t qhf[4][4], qlf[4][4];

    for (int it = 0; it < 32; ++it) {
        if (it < 31) {
            load_kv((it + 1) & 1, it + 1);
            CP_COMMIT();
            CP_WAIT(1);
        } else {
            CP_WAIT(0);
        }
        __syncthreads();

        if (it == 0) {
            #pragma unroll
            for (int ks = 0; ks < 4; ++ks) {
                uint32_t ad = sb + swz((w * 16 + arow) * 128 + ks * 32 + acb);
                ldx4(qhf[ks], ad);
                ldx4(qlf[ks], ad + 16384);
            }
        }

        const uint32_t kb = sb + 32768 + (it & 1) * ASTAGE;

        // ---- S = Q K^T (bf16x3) ----
        float s[8][4];
        #pragma unroll
        for (int i = 0; i < 8; ++i)
            #pragma unroll
            for (int j = 0; j < 4; ++j) s[i][j] = 0.f;

        #pragma unroll
        for (int ks = 0; ks < 4; ++ks)
            #pragma unroll
            for (int ng = 0; ng < 4; ++ng) {
                uint32_t kd = kb + swz((ng * 16 + brow) * 128 + ks * 32 + bcb);
                uint32_t kh[4], kl[4];
                ldx4(kh, kd);
                ldx4(kl, kd + 8192);
                mma16816(s[2*ng],   qhf[ks], kh);     mma16816(s[2*ng],   qhf[ks], kl);
                mma16816(s[2*ng],   qlf[ks], kh);
                mma16816(s[2*ng+1], qhf[ks], kh + 2); mma16816(s[2*ng+1], qhf[ks], kl + 2);
                mma16816(s[2*ng+1], qlf[ks], kh + 2);
            }

        // ---- online softmax (rows g / g+8, reduce over 4 lanes) ----
        float mx0 = -1e30f, mx1 = -1e30f;
        #pragma unroll
        for (int ni = 0; ni < 8; ++ni) {
            mx0 = fmaxf(mx0, fmaxf(s[ni][0], s[ni][1]));
            mx1 = fmaxf(mx1, fmaxf(s[ni][2], s[ni][3]));
        }
        mx0 = fmaxf(mx0, __shfl_xor_sync(0xffffffffu, mx0, 1));
        mx0 = fmaxf(mx0, __shfl_xor_sync(0xffffffffu, mx0, 2));
        mx1 = fmaxf(mx1, __shfl_xor_sync(0xffffffffu, mx1, 1));
        mx1 = fmaxf(mx1, __shfl_xor_sync(0xffffffffu, mx1, 2));
        const float mn0 = fmaxf(mr0, mx0), mn1 = fmaxf(mr1, mx1);
        const float cr0 = __expf(mr0 - mn0), cr1 = __expf(mr1 - mn1);
        mr0 = mn0; mr1 = mn1;

        float sum0 = 0.f, sum1 = 0.f;
        uint32_t ph01[8], ph23[8], pl01[8], pl23[8];
        #pragma unroll
        for (int ni = 0; ni < 8; ++ni) {
            float p0 = __expf(s[ni][0] - mn0), p1 = __expf(s[ni][1] - mn0);
            float p2 = __expf(s[ni][2] - mn1), p3 = __expf(s[ni][3] - mn1);
            sum0 += p0 + p1; sum1 += p2 + p3;
            bf16 h0 = __float2bfloat16(p0), h1 = __float2bfloat16(p1);
            bf16 h2 = __float2bfloat16(p2), h3 = __float2bfloat16(p3);
            __nv_bfloat162 a01 = __halves2bfloat162(h0, h1);
            __nv_bfloat162 a23 = __halves2bfloat162(h2, h3);
            ph01[ni] = reinterpret_cast<uint32_t&>(a01);
            ph23[ni] = reinterpret_cast<uint32_t&>(a23);
            pl01[ni] = packf2(p0 - __bfloat162float(h0), p1 - __bfloat162float(h1));
            pl23[ni] = packf2(p2 - __bfloat162float(h2), p3 - __bfloat162float(h3));
        }
        sum0 += __shfl_xor_sync(0xffffffffu, sum0, 1);
        sum0 += __shfl_xor_sync(0xffffffffu, sum0, 2);
        sum1 += __shfl_xor_sync(0xffffffffu, sum1, 1);
        sum1 += __shfl_xor_sync(0xffffffffu, sum1, 2);
        lr0 = lr0 * cr0 + sum0;
        lr1 = lr1 * cr1 + sum1;
        #pragma unroll
        for (int ni = 0; ni < 8; ++ni) {
            o[ni][0] *= cr0; o[ni][1] *= cr0;
            o[ni][2] *= cr1; o[ni][3] *= cr1;
        }

        // ---- O += P V (bf16x3, V via ldmatrix.trans) ----
        const uint32_t vb = kb + 16384;
        #pragma unroll
        for (int kk = 0; kk < 4; ++kk) {
            uint32_t pa_h[4] = { ph01[2*kk], ph23[2*kk], ph01[2*kk+1], ph23[2*kk+1] };
            uint32_t pa_l[4] = { pl01[2*kk], pl23[2*kk], pl01[2*kk+1], pl23[2*kk+1] };
            #pragma unroll
            for (int dg = 0; dg < 4; ++dg) {
                uint32_t vd = vb + swz((kk * 16 + arow) * 128 + dg * 32 + acb);
                uint32_t vh[4], vl[4];
                ldx4t(vh, vd);
                ldx4t(vl, vd + 8192);
                mma16816(o[2*dg],   pa_h, vh);     mma16816(o[2*dg],   pa_h, vl);
                mma16816(o[2*dg],   pa_l, vh);
                mma16816(o[2*dg+1], pa_h, vh + 2); mma16816(o[2*dg+1], pa_h, vl + 2);
                mma16816(o[2*dg+1], pa_l, vh + 2);
            }
        }
        __syncthreads();
    }

    // ---- epilogue: O /= l, write bf16 hi/lo [m][h*64+d] ----
    const float i0 = 1.f / lr0, i1 = 1.f / lr1;
    const int b = by >> 4, h = by & 15;
    #pragma unroll
    for (int half = 0; half < 2; ++half) {
        const int l = q0 + w * 16 + g + half * 8;
        const size_t mbase = ((size_t)(b * L_ + l)) * INNER_ + h * 64;
        const float inv = half ? i1 : i0;
        #pragma unroll
        for (int ni = 0; ni < 8; ++ni) {
            int d0 = ni * 8 + tq * 2;
            store_hl(g_Oh, g_Ol, mbase + d0,
                     o[ni][half * 2] * inv, o[ni][half * 2 + 1] * inv);
        }
    }
}

// ---------------------------------------------------------------------------
extern "C" void kernel_launch(void* const* d_in, const int* in_sizes, int n_in,
                              void* d_out, int out_size)
{
    const float* x   = (const float*)d_in[0];
    const float* pe  = (const float*)d_in[1];
    const float* Wq  = (const float*)d_in[2];
    const float* Wkv = (const float*)d_in[3];
    const float* Wp  = (const float*)d_in[4];
    const float* bp  = (const float*)d_in[5];
    const float* qs  = (const float*)d_in[6];
    const float* ks  = (const float*)d_in[7];
    float* out = (float*)d_out;

    cudaFuncSetAttribute(qkv_mma,  cudaFuncAttributeMaxDynamicSharedMemorySize, 2 * GSTAGE);
    cudaFuncSetAttribute(proj_mma, cudaFuncAttributeMaxDynamicSharedMemorySize, 2 * GSTAGE);
    cudaFuncSetAttribute(attn_mma, cudaFuncAttributeMaxDynamicSharedMemorySize, ASMEM);

    bf16 *xh, *xl, *wh, *wl, *ph, *pl;
    cudaGetSymbolAddress((void**)&xh, g_xh); cudaGetSymbolAddress((void**)&xl, g_xl);
    cudaGetSymbolAddress((void**)&wh, g_Wh); cudaGetSymbolAddress((void**)&wl, g_Wl);
    cudaGetSymbolAddress((void**)&ph, g_Ph); cudaGetSymbolAddress((void**)&pl, g_Pl);

    split_kernel<<<M_ * QD_ / 4 / 256, 256>>>(x, xh, xl, M_ * QD_ / 4);
    split_kernel<<<INNER_ * QD_ / 4 / 256, 256>>>(Wq, wh, wl, INNER_ * QD_ / 4);
    split_kernel<<<2 * INNER_ * QD_ / 4 / 256, 256>>>(
        Wkv, wh + (size_t)INNER_ * QD_, wl + (size_t)INNER_ * QD_, 2 * INNER_ * QD_ / 4);
    split_kernel<<<QD_ * INNER_ / 4 / 256, 256>>>(Wp, ph, pl, QD_ * INNER_ / 4);

    qkv_mma<<<dim3(M_ / 128, NF_ / 128), 256, 2 * GSTAGE>>>(pe, qs, ks);
    attn_mma<<<dim3(L_ / 128, B_ * H_), 256, ASMEM>>>();
    proj_mma<<<dim3(M_ / 128, QD_ / 128), 256, 2 * GSTAGE>>>(bp, out);
}

// round 4
// speedup vs baseline: 3.8218x; 1.0117x over previous
#include <cuda_runtime.h>
#include <cuda_bf16.h>
#include <cstdint>

#define B_     2
#define L_     2048
#define QD_    1024
#define H_     16
#define D_     64
#define INNER_ 1024
#define M_     4096
#define NF_    3072

typedef __nv_bfloat16 bf16;

// ---------------------------------------------------------------------------
// Scratch (__device__ globals; allocation-free rule)
// ---------------------------------------------------------------------------
__device__ bf16 g_xh[M_ * QD_],  g_xl[M_ * QD_];
__device__ bf16 g_Wh[NF_ * QD_], g_Wl[NF_ * QD_];     // [Wq ; Wkv] fused rows
__device__ bf16 g_Ph[QD_ * INNER_], g_Pl[QD_ * INNER_];
__device__ bf16 g_Qh[M_ * INNER_], g_Ql[M_ * INNER_]; // [b*H+h][l][d]
__device__ bf16 g_Kh[M_ * INNER_], g_Kl[M_ * INNER_];
__device__ bf16 g_Vh[M_ * INNER_], g_Vl[M_ * INNER_];
__device__ bf16 g_Oh[M_ * INNER_], g_Ol[M_ * INNER_]; // [m][h*64+d]

// ---------------------------------------------------------------------------
// Baseline-PTX helpers (legal on .target sm_103 without 'a')
// ---------------------------------------------------------------------------
__device__ __forceinline__ uint32_t smem_u32(const void* p) {
    uint32_t a;
    asm("{ .reg .u64 t; cvta.to.shared.u64 t, %1; cvt.u32.u64 %0, t; }"
        : "=r"(a) : "l"(p));
    return a;
}
__device__ __forceinline__ void cpa16(uint32_t s, const void* g) {
    asm volatile("cp.async.cg.shared.global [%0], [%1], 16;" :: "r"(s), "l"(g));
}
#define CP_COMMIT() asm volatile("cp.async.commit_group;" ::: "memory")
#define CP_WAIT(n)  asm volatile("cp.async.wait_group %0;" :: "n"(n) : "memory")

__device__ __forceinline__ void ldx4(uint32_t r[4], uint32_t a) {
    asm volatile("ldmatrix.sync.aligned.m8n8.x4.shared.b16 {%0,%1,%2,%3}, [%4];"
        : "=r"(r[0]), "=r"(r[1]), "=r"(r[2]), "=r"(r[3]) : "r"(a));
}
__device__ __forceinline__ void ldx4t(uint32_t r[4], uint32_t a) {
    asm volatile("ldmatrix.sync.aligned.m8n8.x4.trans.shared.b16 {%0,%1,%2,%3}, [%4];"
        : "=r"(r[0]), "=r"(r[1]), "=r"(r[2]), "=r"(r[3]) : "r"(a));
}
__device__ __forceinline__ void mma16816(float c[4], const uint32_t a[4],
                                         const uint32_t b[2]) {
    asm volatile(
        "mma.sync.aligned.m16n8k16.row.col.f32.bf16.bf16.f32 "
        "{%0,%1,%2,%3}, {%4,%5,%6,%7}, {%8,%9}, {%0,%1,%2,%3};"
        : "+f"(c[0]), "+f"(c[1]), "+f"(c[2]), "+f"(c[3])
        : "r"(a[0]), "r"(a[1]), "r"(a[2]), "r"(a[3]), "r"(b[0]), "r"(b[1]));
}
__device__ __forceinline__ uint32_t swz(uint32_t o) { return o ^ ((o >> 3) & 0x70); }

__device__ __forceinline__ float ex2f(float x) {
    float y;
    asm("ex2.approx.f32 %0, %1;" : "=f"(y) : "f"(x));
    return y;
}
__device__ __forceinline__ uint32_t packf2(float x, float y) {
    __nv_bfloat162 h = __float22bfloat162_rn(make_float2(x, y));
    return reinterpret_cast<uint32_t&>(h);
}
__device__ __forceinline__ void store_hl(bf16* dh, bf16* dl, size_t idx,
                                         float v0, float v1) {
    bf16 h0 = __float2bfloat16(v0), h1 = __float2bfloat16(v1);
    float l0 = v0 - __bfloat162float(h0), l1 = v1 - __bfloat162float(h1);
    __nv_bfloat162 hh = __halves2bfloat162(h0, h1);
    *reinterpret_cast<uint32_t*>(dh + idx) = reinterpret_cast<uint32_t&>(hh);
    *reinterpret_cast<uint32_t*>(dl + idx) = packf2(l0, l1);
}

// ---------------------------------------------------------------------------
// fp32 -> bf16 hi/lo split
// ---------------------------------------------------------------------------
__global__ __launch_bounds__(256) void split_kernel(
    const float* __restrict__ s, bf16* __restrict__ hi, bf16* __restrict__ lo, int n4)
{
    int i = blockIdx.x * 256 + threadIdx.x;
    if (i >= n4) return;
    float4 v = reinterpret_cast<const float4*>(s)[i];
    store_hl(hi, lo, (size_t)i * 4,     v.x, v.y);
    store_hl(hi, lo, (size_t)i * 4 + 2, v.z, v.w);
}

// ---------------------------------------------------------------------------
// Shared HMMA GEMM mainloop: C[128m x 128n] = A[m][1024] * B[n][1024]^T
// bf16x3, fp32 accum. 3-stage cp.async pipeline, one sync per chunk.
// ---------------------------------------------------------------------------
#define GSTAGE 65536   // Ah 16K | Al 16K | Bh 16K | Bl 16K
#define NCH    16

__device__ __forceinline__ void gemm_main(
    const bf16* __restrict__ Ah, const bf16* __restrict__ Al,
    const bf16* __restrict__ Bh, const bf16* __restrict__ Bl,
    int m0, int n0, char* smem, float c[2][8][4])
{
    const int tid = threadIdx.x;
    const int lane = tid & 31, wid = tid >> 5;
    const int wm = wid & 3, wn = wid >> 2;
    const uint32_t sb = smem_u32(smem);

    const int arow = (lane & 7) + ((lane >> 3) & 1) * 8;
    const int acb  = (lane >> 4) * 16;
    const int brow = (lane & 7) + ((lane >> 4) & 1) * 8;
    const int bcb  = ((lane >> 3) & 1) * 16;

    const bf16* srcs[4] = { Ah + (size_t)m0 * QD_, Al + (size_t)m0 * QD_,
                            Bh + (size_t)n0 * QD_, Bl + (size_t)n0 * QD_ };

    auto load_stage = [&](int st, int ch) {
        uint32_t base = sb + st * GSTAGE;
        #pragma unroll
        for (int mtx = 0; mtx < 4; ++mtx)
            #pragma unroll
            for (int i = 0; i < 4; ++i) {
                int u = tid + i * 256;
                int row = u >> 3, s7 = u & 7;
                cpa16(base + mtx * 16384 + swz(row * 128 + s7 * 16),
                      srcs[mtx] + (size_t)row * QD_ + ch * 64 + s7 * 8);
            }
    };

    load_stage(0, 0); CP_COMMIT();
    load_stage(1, 1); CP_COMMIT();

    for (int ch = 0; ch < NCH; ++ch) {
        if (ch < NCH - 1) { CP_WAIT(1); } else { CP_WAIT(0); }
        __syncthreads();
        if (ch + 2 < NCH) {
            load_stage((ch + 2) % 3, ch + 2);
            CP_COMMIT();
        }

        uint32_t base = sb + (ch % 3) * GSTAGE;
        #pragma unroll
        for (int ks = 0; ks < 4; ++ks) {
            uint32_t ah[2][4], al[2][4];
            #pragma unroll
            for (int mi = 0; mi < 2; ++mi) {
                uint32_t ad = base + swz((wm * 32 + mi * 16 + arow) * 128 + ks * 32 + acb);
                ldx4(ah[mi], ad);
                ldx4(al[mi], ad + 16384);
            }
            uint32_t bhf[8][2], blf[8][2];
            #pragma unroll
            for (int ng = 0; ng < 4; ++ng) {
                uint32_t bd = base + 32768
                            + swz((wn * 64 + ng * 16 + brow) * 128 + ks * 32 + bcb);
                uint32_t r[4];
                ldx4(r, bd);
                bhf[2*ng][0]=r[0]; bhf[2*ng][1]=r[1]; bhf[2*ng+1][0]=r[2]; bhf[2*ng+1][1]=r[3];
                ldx4(r, bd + 16384);
                blf[2*ng][0]=r[0]; blf[2*ng][1]=r[1]; blf[2*ng+1][0]=r[2]; blf[2*ng+1][1]=r[3];
            }
            #pragma unroll
            for (int mi = 0; mi < 2; ++mi)
                #pragma unroll
                for (int ni = 0; ni < 8; ++ni) {
                    mma16816(c[mi][ni], ah[mi], bhf[ni]);
                    mma16816(c[mi][ni], ah[mi], blf[ni]);
                    mma16816(c[mi][ni], al[mi], bhf[ni]);
                }
        }
    }
}

// ---------------------------------------------------------------------------
// QKV projection GEMM + RMSNorm + RoPE, writes Q/K/V bf16 hi/lo
// Q additionally scaled by 0.125 * log2(e)  (softmax runs in exp2 domain)
// ---------------------------------------------------------------------------
__global__ __launch_bounds__(256, 1) void qkv_mma(
    const float* __restrict__ pe,
    const float* __restrict__ qsc, const float* __restrict__ ksc)
{
    extern __shared__ char smem[];
    const int m0 = blockIdx.x * 128, n0 = blockIdx.y * 128;
    float c[2][8][4];
    #pragma unroll
    for (int i = 0; i < 2; ++i)
        #pragma unroll
        for (int j = 0; j < 8; ++j)
            #pragma unroll
            for (int k = 0; k < 4; ++k) c[i][j][k] = 0.f;

    gemm_main(g_xh, g_xl, g_Wh, g_Wl, m0, n0, smem, c);

    const int tid = threadIdx.x, lane = tid & 31, wid = tid >> 5;
    const int wm = wid & 3, wn = wid >> 2;
    const int tq = lane & 3, g = lane >> 2;

    const int f0 = n0 + wn * 64;
    const int kind = f0 >> 10;               // 0:Q 1:K 2:V
    const int h = (f0 & 1023) >> 6;
    bf16* dh = (kind == 0) ? g_Qh : (kind == 1) ? g_Kh : g_Vh;
    bf16* dl = (kind == 0) ? g_Ql : (kind == 1) ? g_Kl : g_Vl;
    const float* sc = (kind == 0) ? qsc : ksc;
    const float qm = (kind == 0) ? 0.125f * 1.4426950408889634f : 1.f;

    #pragma unroll
    for (int mi = 0; mi < 2; ++mi)
        #pragma unroll
        for (int half = 0; half < 2; ++half) {
            const int m = m0 + wm * 32 + mi * 16 + g + half * 8;
            const int b = m >> 11, l = m & 2047;
            const size_t obase = ((size_t)(b * H_ + h) * L_ + l) * 64;

            if (kind == 2) {
                #pragma unroll
                for (int ni = 0; ni < 8; ++ni) {
                    int d0 = ni * 8 + tq * 2;
                    store_hl(dh, dl, obase + d0,
                             c[mi][ni][half * 2], c[mi][ni][half * 2 + 1]);
                }
            } else {
                float ss = 0.f;
                #pragma unroll
                for (int ni = 0; ni < 8; ++ni) {
                    float v0 = c[mi][ni][half * 2], v1 = c[mi][ni][half * 2 + 1];
                    ss = fmaf(v0, v0, fmaf(v1, v1, ss));
                }
                ss += __shfl_xor_sync(0xffffffffu, ss, 1);
                ss += __shfl_xor_sync(0xffffffffu, ss, 2);
                const float rr = rsqrtf(ss * (1.f / 64.f) + 1e-6f);
                const float* pel = pe + (size_t)l * 128;
                #pragma unroll
                for (int ni = 0; ni < 8; ++ni) {
                    int d0 = ni * 8 + tq * 2;
                    float v0 = c[mi][ni][half * 2]     * rr * sc[d0];
                    float v1 = c[mi][ni][half * 2 + 1] * rr * sc[d0 + 1];
                    float4 p = *reinterpret_cast<const float4*>(pel + (d0 >> 1) * 4);
                    float o0 = (p.x * v0 + p.y * v1) * qm;
                    float o1 = (p.z * v0 + p.w * v1) * qm;
                    store_hl(dh, dl, obase + d0, o0, o1);
                }
            }
        }
}

// ---------------------------------------------------------------------------
// Output projection GEMM + bias -> fp32 out
// ---------------------------------------------------------------------------
__global__ __launch_bounds__(256, 1) void proj_mma(
    const float* __restrict__ bp, float* __restrict__ out)
{
    extern __shared__ char smem[];
    const int m0 = blockIdx.x * 128, n0 = blockIdx.y * 128;
    float c[2][8][4];
    #pragma unroll
    for (int i = 0; i < 2; ++i)
        #pragma unroll
        for (int j = 0; j < 8; ++j)
            #pragma unroll
            for (int k = 0; k < 4; ++k) c[i][j][k] = 0.f;

    gemm_main(g_Oh, g_Ol, g_Ph, g_Pl, m0, n0, smem, c);

    const int tid = threadIdx.x, lane = tid & 31, wid = tid >> 5;
    const int wm = wid & 3, wn = wid >> 2;
    const int tq = lane & 3, g = lane >> 2;

    #pragma unroll
    for (int mi = 0; mi < 2; ++mi)
        #pragma unroll
        for (int half = 0; half < 2; ++half) {
            const int m = m0 + wm * 32 + mi * 16 + g + half * 8;
            #pragma unroll
            for (int ni = 0; ni < 8; ++ni) {
                int col = n0 + wn * 64 + ni * 8 + tq * 2;
                float2 bv = *reinterpret_cast<const float2*>(bp + col);
                float2 o = make_float2(c[mi][ni][half * 2]     + bv.x,
                                       c[mi][ni][half * 2 + 1] + bv.y);
                *reinterpret_cast<float2*>(out + (size_t)m * QD_ + col) = o;
            }
        }
}

// ---------------------------------------------------------------------------
// Flash attention, HMMA bf16x3, online softmax in exp2 domain
//   grid = (L_/128, B_*H_), 256 threads; 3-stage KV pipeline
//   smem: Qh 16K | Ql 16K | 3 stages x (Kh 8K | Kl 8K | Vh 8K | Vl 8K)
// ---------------------------------------------------------------------------
#define ASTAGE 32768
#define ASMEM  (32768 + 3 * ASTAGE)
#define NIT    32

__global__ __launch_bounds__(256, 1) void attn_mma()
{
    extern __shared__ char smem[];
    const int tid = threadIdx.x, lane = tid & 31, w = tid >> 5;
    const int by = blockIdx.y;
    const int q0 = blockIdx.x * 128;
    const uint32_t sb = smem_u32(smem);

    const bf16* Qhp = g_Qh + ((size_t)by * L_ + q0) * 64;
    const bf16* Qlp = g_Ql + ((size_t)by * L_ + q0) * 64;
    const bf16* Khp = g_Kh + (size_t)by * L_ * 64;
    const bf16* Klp = g_Kl + (size_t)by * L_ * 64;
    const bf16* Vhp = g_Vh + (size_t)by * L_ * 64;
    const bf16* Vlp = g_Vl + (size_t)by * L_ * 64;

    const int tq = lane & 3, g = lane >> 2;
    const int arow = (lane & 7) + ((lane >> 3) & 1) * 8;
    const int acb  = (lane >> 4) * 16;
    const int brow = (lane & 7) + ((lane >> 4) & 1) * 8;
    const int bcb  = ((lane >> 3) & 1) * 16;

    auto load_kv = [&](int st, int kt) {
        uint32_t base = sb + 32768 + st * ASTAGE;
        const bf16* srcs[4] = { Khp, Klp, Vhp, Vlp };
        #pragma unroll
        for (int mtx = 0; mtx < 4; ++mtx)
            #pragma unroll
            for (int i = 0; i < 2; ++i) {
                int u = tid + i * 256;
                int row = u >> 3, s7 = u & 7;
                cpa16(base + mtx * 8192 + swz(row * 128 + s7 * 16),
                      srcs[mtx] + (size_t)(kt * 64 + row) * 64 + s7 * 8);
            }
    };

    // prologue: Q + KV stage0 (group0), KV stage1 (group1)
    #pragma unroll
    for (int i = 0; i < 4; ++i) {
        int u = tid + i * 256;
        int row = u >> 3, s7 = u & 7;
        cpa16(sb +         swz(row * 128 + s7 * 16), Qhp + (size_t)row * 64 + s7 * 8);
        cpa16(sb + 16384 + swz(row * 128 + s7 * 16), Qlp + (size_t)row * 64 + s7 * 8);
    }
    load_kv(0, 0); CP_COMMIT();
    load_kv(1, 1); CP_COMMIT();

    float o[8][4];
    #pragma unroll
    for (int i = 0; i < 8; ++i)
        #pragma unroll
        for (int j = 0; j < 4; ++j) o[i][j] = 0.f;
    float mr0 = -1e30f, mr1 = -1e30f, lr0 = 0.f, lr1 = 0.f;
    uint32_t qhf[4][4], qlf[4][4];

    for (int it = 0; it < NIT; ++it) {
        if (it < NIT - 1) { CP_WAIT(1); } else { CP_WAIT(0); }
        __syncthreads();
        if (it + 2 < NIT) {
            load_kv((it + 2) % 3, it + 2);
            CP_COMMIT();
        }

        if (it == 0) {
            #pragma unroll
            for (int ks = 0; ks < 4; ++ks) {
                uint32_t ad = sb + swz((w * 16 + arow) * 128 + ks * 32 + acb);
                ldx4(qhf[ks], ad);
                ldx4(qlf[ks], ad + 16384);
            }
        }

        const uint32_t kb = sb + 32768 + (it % 3) * ASTAGE;

        // ---- S = Q K^T (bf16x3), scores already in log2 domain ----
        float s[8][4];
        #pragma unroll
        for (int i = 0; i < 8; ++i)
            #pragma unroll
            for (int j = 0; j < 4; ++j) s[i][j] = 0.f;

        #pragma unroll
        for (int ks = 0; ks < 4; ++ks)
            #pragma unroll
            for (int ng = 0; ng < 4; ++ng) {
                uint32_t kd = kb + swz((ng * 16 + brow) * 128 + ks * 32 + bcb);
                uint32_t kh[4], kl[4];
                ldx4(kh, kd);
                ldx4(kl, kd + 8192);
                mma16816(s[2*ng],   qhf[ks], kh);     mma16816(s[2*ng],   qhf[ks], kl);
                mma16816(s[2*ng],   qlf[ks], kh);
                mma16816(s[2*ng+1], qhf[ks], kh + 2); mma16816(s[2*ng+1], qhf[ks], kl + 2);
                mma16816(s[2*ng+1], qlf[ks], kh + 2);
            }

        // ---- online softmax (exp2 domain) ----
        float mx0 = -1e30f, mx1 = -1e30f;
        #pragma unroll
        for (int ni = 0; ni < 8; ++ni) {
            mx0 = fmaxf(mx0, fmaxf(s[ni][0], s[ni][1]));
            mx1 = fmaxf(mx1, fmaxf(s[ni][2], s[ni][3]));
        }
        mx0 = fmaxf(mx0, __shfl_xor_sync(0xffffffffu, mx0, 1));
        mx0 = fmaxf(mx0, __shfl_xor_sync(0xffffffffu, mx0, 2));
        mx1 = fmaxf(mx1, __shfl_xor_sync(0xffffffffu, mx1, 1));
        mx1 = fmaxf(mx1, __shfl_xor_sync(0xffffffffu, mx1, 2));
        const float mn0 = fmaxf(mr0, mx0), mn1 = fmaxf(mr1, mx1);
        const float cr0 = ex2f(mr0 - mn0), cr1 = ex2f(mr1 - mn1);
        mr0 = mn0; mr1 = mn1;

        float sum0 = 0.f, sum1 = 0.f;
        uint32_t ph01[8], ph23[8], pl01[8], pl23[8];
        #pragma unroll
        for (int ni = 0; ni < 8; ++ni) {
            float p0 = ex2f(s[ni][0] - mn0), p1 = ex2f(s[ni][1] - mn0);
            float p2 = ex2f(s[ni][2] - mn1), p3 = ex2f(s[ni][3] - mn1);
            sum0 += p0 + p1; sum1 += p2 + p3;
            bf16 h0 = __float2bfloat16(p0), h1 = __float2bfloat16(p1);
            bf16 h2 = __float2bfloat16(p2), h3 = __float2bfloat16(p3);
            __nv_bfloat162 a01 = __halves2bfloat162(h0, h1);
            __nv_bfloat162 a23 = __halves2bfloat162(h2, h3);
            ph01[ni] = reinterpret_cast<uint32_t&>(a01);
            ph23[ni] = reinterpret_cast<uint32_t&>(a23);
            pl01[ni] = packf2(p0 - __bfloat162float(h0), p1 - __bfloat162float(h1));
            pl23[ni] = packf2(p2 - __bfloat162float(h2), p3 - __bfloat162float(h3));
        }
        sum0 += __shfl_xor_sync(0xffffffffu, sum0, 1);
        sum0 += __shfl_xor_sync(0xffffffffu, sum0, 2);
        sum1 += __shfl_xor_sync(0xffffffffu, sum1, 1);
        sum1 += __shfl_xor_sync(0xffffffffu, sum1, 2);
        lr0 = lr0 * cr0 + sum0;
        lr1 = lr1 * cr1 + sum1;
        #pragma unroll
        for (int ni = 0; ni < 8; ++ni) {
            o[ni][0] *= cr0; o[ni][1] *= cr0;
            o[ni][2] *= cr1; o[ni][3] *= cr1;
        }

        // ---- O += P V (bf16x3, V via ldmatrix.trans) ----
        const uint32_t vb = kb + 16384;
        #pragma unroll
        for (int kk = 0; kk < 4; ++kk) {
            uint32_t pa_h[4] = { ph01[2*kk], ph23[2*kk], ph01[2*kk+1], ph23[2*kk+1] };
            uint32_t pa_l[4] = { pl01[2*kk], pl23[2*kk], pl01[2*kk+1], pl23[2*kk+1] };
            #pragma unroll
            for (int dg = 0; dg < 4; ++dg) {
                uint32_t vd = vb + swz((kk * 16 + arow) * 128 + dg * 32 + acb);
                uint32_t vh[4], vl[4];
                ldx4t(vh, vd);
                ldx4t(vl, vd + 8192);
                mma16816(o[2*dg],   pa_h, vh);     mma16816(o[2*dg],   pa_h, vl);
                mma16816(o[2*dg],   pa_l, vh);
                mma16816(o[2*dg+1], pa_h, vh + 2); mma16816(o[2*dg+1], pa_h, vl + 2);
                mma16816(o[2*dg+1], pa_l, vh + 2);
            }
        }
    }

    // ---- epilogue ----
    const float i0 = 1.f / lr0, i1 = 1.f / lr1;
    const int b = by >> 4, h = by & 15;
    #pragma unroll
    for (int half = 0; half < 2; ++half) {
        const int l = q0 + w * 16 + g + half * 8;
        const size_t mbase = ((size_t)(b * L_ + l)) * INNER_ + h * 64;
        const float inv = half ? i1 : i0;
        #pragma unroll
        for (int ni = 0; ni < 8; ++ni) {
            int d0 = ni * 8 + tq * 2;
            store_hl(g_Oh, g_Ol, mbase + d0,
                     o[ni][half * 2] * inv, o[ni][half * 2 + 1] * inv);
        }
    }
}

// ---------------------------------------------------------------------------
extern "C" void kernel_launch(void* const* d_in, const int* in_sizes, int n_in,
                              void* d_out, int out_size)
{
    const float* x   = (const float*)d_in[0];
    const float* pe  = (const float*)d_in[1];
    const float* Wq  = (const float*)d_in[2];
    const float* Wkv = (const float*)d_in[3];
    const float* Wp  = (const float*)d_in[4];
    const float* bp  = (const float*)d_in[5];
    const float* qs  = (const float*)d_in[6];
    const float* ks  = (const float*)d_in[7];
    float* out = (float*)d_out;

    cudaFuncSetAttribute(qkv_mma,  cudaFuncAttributeMaxDynamicSharedMemorySize, 3 * GSTAGE);
    cudaFuncSetAttribute(proj_mma, cudaFuncAttributeMaxDynamicSharedMemorySize, 3 * GSTAGE);
    cudaFuncSetAttribute(attn_mma, cudaFuncAttributeMaxDynamicSharedMemorySize, ASMEM);

    bf16 *xh, *xl, *wh, *wl, *ph, *pl;
    cudaGetSymbolAddress((void**)&xh, g_xh); cudaGetSymbolAddress((void**)&xl, g_xl);
    cudaGetSymbolAddress((void**)&wh, g_Wh); cudaGetSymbolAddress((void**)&wl, g_Wl);
    cudaGetSymbolAddress((void**)&ph, g_Ph); cudaGetSymbolAddress((void**)&pl, g_Pl);

    split_kernel<<<M_ * QD_ / 4 / 256, 256>>>(x, xh, xl, M_ * QD_ / 4);
    split_kernel<<<INNER_ * QD_ / 4 / 256, 256>>>(Wq, wh, wl, INNER_ * QD_ / 4);
    split_kernel<<<2 * INNER_ * QD_ / 4 / 256, 256>>>(
        Wkv, wh + (size_t)INNER_ * QD_, wl + (size_t)INNER_ * QD_, 2 * INNER_ * QD_ / 4);
    split_kernel<<<QD_ * INNER_ / 4 / 256, 256>>>(Wp, ph, pl, QD_ * INNER_ / 4);

    qkv_mma<<<dim3(M_ / 128, NF_ / 128), 256, 3 * GSTAGE>>>(pe, qs, ks);
    attn_mma<<<dim3(L_ / 128, B_ * H_), 256, ASMEM>>>();
    proj_mma<<<dim3(M_ / 128, QD_ / 128), 256, 3 * GSTAGE>>>(bp, out);
}

// round 5
// speedup vs baseline: 4.2715x; 1.1177x over previous
#include <cuda_runtime.h>
#include <cuda_bf16.h>
#include <cstdint>

#define B_     2
#define L_     2048
#define QD_    1024
#define H_     16
#define D_     64
#define INNER_ 1024
#define M_     4096
#define NF_    3072

typedef __nv_bfloat16 bf16;

// ---------------------------------------------------------------------------
// Scratch (__device__ globals; allocation-free rule)
// ---------------------------------------------------------------------------
__device__ bf16 g_xh[M_ * QD_],  g_xl[M_ * QD_];
__device__ bf16 g_Wh[NF_ * QD_], g_Wl[NF_ * QD_];     // [Wq ; Wkv] fused rows
__device__ bf16 g_Ph[QD_ * INNER_], g_Pl[QD_ * INNER_];
__device__ bf16 g_Qh[M_ * INNER_], g_Ql[M_ * INNER_]; // [b*H+h][l][d]
__device__ bf16 g_Kh[M_ * INNER_], g_Kl[M_ * INNER_];
__device__ bf16 g_Vh[M_ * INNER_], g_Vl[M_ * INNER_];
__device__ bf16 g_Oh[M_ * INNER_], g_Ol[M_ * INNER_]; // [m][h*64+d]

// ---------------------------------------------------------------------------
// Baseline-PTX helpers
// ---------------------------------------------------------------------------
__device__ __forceinline__ uint32_t smem_u32(const void* p) {
    uint32_t a;
    asm("{ .reg .u64 t; cvta.to.shared.u64 t, %1; cvt.u32.u64 %0, t; }"
        : "=r"(a) : "l"(p));
    return a;
}
__device__ __forceinline__ void cpa16(uint32_t s, const void* g) {
    asm volatile("cp.async.cg.shared.global [%0], [%1], 16;" :: "r"(s), "l"(g));
}
#define CP_COMMIT() asm volatile("cp.async.commit_group;" ::: "memory")
#define CP_WAIT(n)  asm volatile("cp.async.wait_group %0;" :: "n"(n) : "memory")

__device__ __forceinline__ void ldx4(uint32_t r[4], uint32_t a) {
    asm volatile("ldmatrix.sync.aligned.m8n8.x4.shared.b16 {%0,%1,%2,%3}, [%4];"
        : "=r"(r[0]), "=r"(r[1]), "=r"(r[2]), "=r"(r[3]) : "r"(a));
}
__device__ __forceinline__ void ldx4t(uint32_t r[4], uint32_t a) {
    asm volatile("ldmatrix.sync.aligned.m8n8.x4.trans.shared.b16 {%0,%1,%2,%3}, [%4];"
        : "=r"(r[0]), "=r"(r[1]), "=r"(r[2]), "=r"(r[3]) : "r"(a));
}
__device__ __forceinline__ void mma16816(float c[4], const uint32_t a[4],
                                         const uint32_t b[2]) {
    asm volatile(
        "mma.sync.aligned.m16n8k16.row.col.f32.bf16.bf16.f32 "
        "{%0,%1,%2,%3}, {%4,%5,%6,%7}, {%8,%9}, {%0,%1,%2,%3};"
        : "+f"(c[0]), "+f"(c[1]), "+f"(c[2]), "+f"(c[3])
        : "r"(a[0]), "r"(a[1]), "r"(a[2]), "r"(a[3]), "r"(b[0]), "r"(b[1]));
}
__device__ __forceinline__ uint32_t swz(uint32_t o) { return o ^ ((o >> 3) & 0x70); }

__device__ __forceinline__ float ex2f(float x) {
    float y;
    asm("ex2.approx.f32 %0, %1;" : "=f"(y) : "f"(x));
    return y;
}
__device__ __forceinline__ uint32_t packf2(float x, float y) {
    __nv_bfloat162 h = __float22bfloat162_rn(make_float2(x, y));
    return reinterpret_cast<uint32_t&>(h);
}
__device__ __forceinline__ void store_hl(bf16* dh, bf16* dl, size_t idx,
                                         float v0, float v1) {
    bf16 h0 = __float2bfloat16(v0), h1 = __float2bfloat16(v1);
    float l0 = v0 - __bfloat162float(h0), l1 = v1 - __bfloat162float(h1);
    __nv_bfloat162 hh = __halves2bfloat162(h0, h1);
    *reinterpret_cast<uint32_t*>(dh + idx) = reinterpret_cast<uint32_t&>(hh);
    *reinterpret_cast<uint32_t*>(dl + idx) = packf2(l0, l1);
}

// ---------------------------------------------------------------------------
// fp32 -> bf16 hi/lo split
// ---------------------------------------------------------------------------
__global__ __launch_bounds__(256) void split_kernel(
    const float* __restrict__ s, bf16* __restrict__ hi, bf16* __restrict__ lo, int n4)
{
    int i = blockIdx.x * 256 + threadIdx.x;
    if (i >= n4) return;
    float4 v = reinterpret_cast<const float4*>(s)[i];
    store_hl(hi, lo, (size_t)i * 4,     v.x, v.y);
    store_hl(hi, lo, (size_t)i * 4 + 2, v.z, v.w);
}

// ---------------------------------------------------------------------------
// HMMA GEMM mainloop: C[128m x 64n] = A[m][1024] * B[n][1024]^T, bf16x3.
// 8 warps, warp tile m16 x n64. 2-stage cp.async (96KB) -> 2 CTAs/SM.
// Stage: Ah 16K | Al 16K | Bh 8K | Bl 8K = 48K
// ---------------------------------------------------------------------------
#define GSTAGE 49152
#define NCH    16

__device__ __forceinline__ void gemm_main(
    const bf16* __restrict__ Ah, const bf16* __restrict__ Al,
    const bf16* __restrict__ Bh, const bf16* __restrict__ Bl,
    int m0, int n0, char* smem, float c[8][4])
{
    const int tid = threadIdx.x;
    const int lane = tid & 31, w = tid >> 5;
    const uint32_t sb = smem_u32(smem);

    const int arow = (lane & 7) + ((lane >> 3) & 1) * 8;
    const int acb  = (lane >> 4) * 16;
    const int brow = (lane & 7) + ((lane >> 4) & 1) * 8;
    const int bcb  = ((lane >> 3) & 1) * 16;

    const bf16* Ahp = Ah + (size_t)m0 * QD_;
    const bf16* Alp = Al + (size_t)m0 * QD_;
    const bf16* Bhp = Bh + (size_t)n0 * QD_;
    const bf16* Blp = Bl + (size_t)n0 * QD_;

    auto load_stage = [&](int st, int ch) {
        uint32_t base = sb + st * GSTAGE;
        #pragma unroll
        for (int i = 0; i < 4; ++i) {           // A: 128 rows x 128B, hi+lo
            int u = tid + i * 256;
            int row = u >> 3, s7 = u & 7;
            uint32_t so = swz(row * 128 + s7 * 16);
            cpa16(base + so,         Ahp + (size_t)row * QD_ + ch * 64 + s7 * 8);
            cpa16(base + 16384 + so, Alp + (size_t)row * QD_ + ch * 64 + s7 * 8);
        }
        #pragma unroll
        for (int i = 0; i < 2; ++i) {           // B: 64 rows x 128B, hi+lo
            int u = tid + i * 256;
            int row = u >> 3, s7 = u & 7;
            uint32_t so = swz(row * 128 + s7 * 16);
            cpa16(base + 32768 + so, Bhp + (size_t)row * QD_ + ch * 64 + s7 * 8);
            cpa16(base + 40960 + so, Blp + (size_t)row * QD_ + ch * 64 + s7 * 8);
        }
    };

    load_stage(0, 0); CP_COMMIT();

    for (int ch = 0; ch < NCH; ++ch) {
        CP_WAIT(0);
        __syncthreads();
        if (ch + 1 < NCH) {
            load_stage((ch + 1) & 1, ch + 1);
            CP_COMMIT();
        }

        uint32_t base = sb + (ch & 1) * GSTAGE;
        #pragma unroll
        for (int ks = 0; ks < 4; ++ks) {
            uint32_t ah[4], al[4];
            uint32_t ad = base + swz((w * 16 + arow) * 128 + ks * 32 + acb);
            ldx4(ah, ad);
            ldx4(al, ad + 16384);
            #pragma unroll
            for (int ng = 0; ng < 4; ++ng) {
                uint32_t bd = base + 32768
                            + swz((ng * 16 + brow) * 128 + ks * 32 + bcb);
                uint32_t bh[4], bl[4];
                ldx4(bh, bd);
                ldx4(bl, bd + 8192);
                mma16816(c[2*ng],   ah, bh);     mma16816(c[2*ng],   ah, bl);
                mma16816(c[2*ng],   al, bh);
                mma16816(c[2*ng+1], ah, bh + 2); mma16816(c[2*ng+1], ah, bl + 2);
                mma16816(c[2*ng+1], al, bh + 2);
            }
        }
    }
}

// ---------------------------------------------------------------------------
// QKV projection GEMM + RMSNorm + RoPE -> Q/K/V bf16 hi/lo
//   grid = (M_/128, NF_/64), 256 threads; one head per CTA column-tile
// ---------------------------------------------------------------------------
__global__ __launch_bounds__(256, 2) void qkv_mma(
    const float* __restrict__ pe,
    const float* __restrict__ qsc, const float* __restrict__ ksc)
{
    extern __shared__ char smem[];
    const int m0 = blockIdx.x * 128, n0 = blockIdx.y * 64;
    float c[8][4];
    #pragma unroll
    for (int j = 0; j < 8; ++j)
        #pragma unroll
        for (int k = 0; k < 4; ++k) c[j][k] = 0.f;

    gemm_main(g_xh, g_xl, g_Wh, g_Wl, m0, n0, smem, c);

    const int tid = threadIdx.x, lane = tid & 31, w = tid >> 5;
    const int tq = lane & 3, g = lane >> 2;

    const int kind = n0 >> 10;               // 0:Q 1:K 2:V
    const int h = (n0 & 1023) >> 6;
    bf16* dh = (kind == 0) ? g_Qh : (kind == 1) ? g_Kh : g_Vh;
    bf16* dl = (kind == 0) ? g_Ql : (kind == 1) ? g_Kl : g_Vl;
    const float* sc = (kind == 0) ? qsc : ksc;
    const float qm = (kind == 0) ? 0.125f * 1.4426950408889634f : 1.f;

    #pragma unroll
    for (int half = 0; half < 2; ++half) {
        const int m = m0 + w * 16 + g + half * 8;
        const int b = m >> 11, l = m & 2047;
        const size_t obase = ((size_t)(b * H_ + h) * L_ + l) * 64;

        if (kind == 2) {
            #pragma unroll
            for (int ni = 0; ni < 8; ++ni) {
                int d0 = ni * 8 + tq * 2;
                store_hl(dh, dl, obase + d0, c[ni][half * 2], c[ni][half * 2 + 1]);
            }
        } else {
            float ss = 0.f;
            #pragma unroll
            for (int ni = 0; ni < 8; ++ni) {
                float v0 = c[ni][half * 2], v1 = c[ni][half * 2 + 1];
                ss = fmaf(v0, v0, fmaf(v1, v1, ss));
            }
            ss += __shfl_xor_sync(0xffffffffu, ss, 1);
            ss += __shfl_xor_sync(0xffffffffu, ss, 2);
            const float rr = rsqrtf(ss * (1.f / 64.f) + 1e-6f);
            const float* pel = pe + (size_t)l * 128;
            #pragma unroll
            for (int ni = 0; ni < 8; ++ni) {
                int d0 = ni * 8 + tq * 2;
                float v0 = c[ni][half * 2]     * rr * sc[d0];
                float v1 = c[ni][half * 2 + 1] * rr * sc[d0 + 1];
                float4 p = *reinterpret_cast<const float4*>(pel + (d0 >> 1) * 4);
                float o0 = (p.x * v0 + p.y * v1) * qm;
                float o1 = (p.z * v0 + p.w * v1) * qm;
                store_hl(dh, dl, obase + d0, o0, o1);
            }
        }
    }
}

// ---------------------------------------------------------------------------
// Output projection GEMM + bias -> fp32 out
//   grid = (M_/128, QD_/64), 256 threads
// ---------------------------------------------------------------------------
__global__ __launch_bounds__(256, 2) void proj_mma(
    const float* __restrict__ bp, float* __restrict__ out)
{
    extern __shared__ char smem[];
    const int m0 = blockIdx.x * 128, n0 = blockIdx.y * 64;
    float c[8][4];
    #pragma unroll
    for (int j = 0; j < 8; ++j)
        #pragma unroll
        for (int k = 0; k < 4; ++k) c[j][k] = 0.f;

    gemm_main(g_Oh, g_Ol, g_Ph, g_Pl, m0, n0, smem, c);

    const int tid = threadIdx.x, lane = tid & 31, w = tid >> 5;
    const int tq = lane & 3, g = lane >> 2;

    #pragma unroll
    for (int half = 0; half < 2; ++half) {
        const int m = m0 + w * 16 + g + half * 8;
        #pragma unroll
        for (int ni = 0; ni < 8; ++ni) {
            int col = n0 + ni * 8 + tq * 2;
            float2 bv = *reinterpret_cast<const float2*>(bp + col);
            float2 o = make_float2(c[ni][half * 2]     + bv.x,
                                   c[ni][half * 2 + 1] + bv.y);
            *reinterpret_cast<float2*>(out + (size_t)m * QD_ + col) = o;
        }
    }
}

// ---------------------------------------------------------------------------
// Flash attention, HMMA bf16x3, exp2-domain online softmax
//   grid = (L_/64, B_*H_), 128 threads (4 warps x 16 q-rows)
//   smem: Qh 8K | Ql 8K | 2 stages x (Kh 8K | Kl 8K | Vh 8K | Vl 8K) = 80K
//   -> 2 CTAs/SM
// ---------------------------------------------------------------------------
#define ASTAGE 32768
#define ASMEM  (16384 + 2 * ASTAGE)
#define NIT    32

__global__ __launch_bounds__(128, 2) void attn_mma()
{
    extern __shared__ char smem[];
    const int tid = threadIdx.x, lane = tid & 31, w = tid >> 5;
    const int by = blockIdx.y;
    const int q0 = blockIdx.x * 64;
    const uint32_t sb = smem_u32(smem);

    const bf16* Qhp = g_Qh + ((size_t)by * L_ + q0) * 64;
    const bf16* Qlp = g_Ql + ((size_t)by * L_ + q0) * 64;
    const bf16* Khp = g_Kh + (size_t)by * L_ * 64;
    const bf16* Klp = g_Kl + (size_t)by * L_ * 64;
    const bf16* Vhp = g_Vh + (size_t)by * L_ * 64;
    const bf16* Vlp = g_Vl + (size_t)by * L_ * 64;

    const int tq = lane & 3, g = lane >> 2;
    const int arow = (lane & 7) + ((lane >> 3) & 1) * 8;
    const int acb  = (lane >> 4) * 16;
    const int brow = (lane & 7) + ((lane >> 4) & 1) * 8;
    const int bcb  = ((lane >> 3) & 1) * 16;

    auto load_kv = [&](int st, int kt) {
        uint32_t base = sb + 16384 + st * ASTAGE;
        const bf16* srcs[4] = { Khp, Klp, Vhp, Vlp };
        #pragma unroll
        for (int mtx = 0; mtx < 4; ++mtx)
            #pragma unroll
            for (int i = 0; i < 4; ++i) {
                int u = tid + i * 128;
                int row = u >> 3, s7 = u & 7;
                cpa16(base + mtx * 8192 + swz(row * 128 + s7 * 16),
                      srcs[mtx] + (size_t)(kt * 64 + row) * 64 + s7 * 8);
            }
    };

    // prologue: Q + KV stage0 in group 0
    #pragma unroll
    for (int i = 0; i < 4; ++i) {
        int u = tid + i * 128;
        int row = u >> 3, s7 = u & 7;
        uint32_t so = swz(row * 128 + s7 * 16);
        cpa16(sb +        so, Qhp + (size_t)row * 64 + s7 * 8);
        cpa16(sb + 8192 + so, Qlp + (size_t)row * 64 + s7 * 8);
    }
    load_kv(0, 0); CP_COMMIT();

    float o[8][4];
    #pragma unroll
    for (int i = 0; i < 8; ++i)
        #pragma unroll
        for (int j = 0; j < 4; ++j) o[i][j] = 0.f;
    float mr0 = -1e30f, mr1 = -1e30f, lr0 = 0.f, lr1 = 0.f;
    uint32_t qhf[4][4], qlf[4][4];

    for (int it = 0; it < NIT; ++it) {
        CP_WAIT(0);
        __syncthreads();
        if (it + 1 < NIT) {
            load_kv((it + 1) & 1, it + 1);
            CP_COMMIT();
        }

        if (it == 0) {
            #pragma unroll
            for (int ks = 0; ks < 4; ++ks) {
                uint32_t ad = sb + swz((w * 16 + arow) * 128 + ks * 32 + acb);
                ldx4(qhf[ks], ad);
                ldx4(qlf[ks], ad + 8192);
            }
        }

        const uint32_t kb = sb + 16384 + (it & 1) * ASTAGE;

        // ---- S = Q K^T (bf16x3, log2 domain) ----
        float s[8][4];
        #pragma unroll
        for (int i = 0; i < 8; ++i)
            #pragma unroll
            for (int j = 0; j < 4; ++j) s[i][j] = 0.f;

        #pragma unroll
        for (int ks = 0; ks < 4; ++ks)
            #pragma unroll
            for (int ng = 0; ng < 4; ++ng) {
                uint32_t kd = kb + swz((ng * 16 + brow) * 128 + ks * 32 + bcb);
                uint32_t kh[4], kl[4];
                ldx4(kh, kd);
                ldx4(kl, kd + 8192);
                mma16816(s[2*ng],   qhf[ks], kh);     mma16816(s[2*ng],   qhf[ks], kl);
                mma16816(s[2*ng],   qlf[ks], kh);
                mma16816(s[2*ng+1], qhf[ks], kh + 2); mma16816(s[2*ng+1], qhf[ks], kl + 2);
                mma16816(s[2*ng+1], qlf[ks], kh + 2);
            }

        // ---- online softmax (exp2 domain) ----
        float mx0 = -1e30f, mx1 = -1e30f;
        #pragma unroll
        for (int ni = 0; ni < 8; ++ni) {
            mx0 = fmaxf(mx0, fmaxf(s[ni][0], s[ni][1]));
            mx1 = fmaxf(mx1, fmaxf(s[ni][2], s[ni][3]));
        }
        mx0 = fmaxf(mx0, __shfl_xor_sync(0xffffffffu, mx0, 1));
        mx0 = fmaxf(mx0, __shfl_xor_sync(0xffffffffu, mx0, 2));
        mx1 = fmaxf(mx1, __shfl_xor_sync(0xffffffffu, mx1, 1));
        mx1 = fmaxf(mx1, __shfl_xor_sync(0xffffffffu, mx1, 2));
        const float mn0 = fmaxf(mr0, mx0), mn1 = fmaxf(mr1, mx1);
        const float cr0 = ex2f(mr0 - mn0), cr1 = ex2f(mr1 - mn1);
        mr0 = mn0; mr1 = mn1;

        float sum0 = 0.f, sum1 = 0.f;
        uint32_t ph01[8], ph23[8], pl01[8], pl23[8];
        #pragma unroll
        for (int ni = 0; ni < 8; ++ni) {
            float p0 = ex2f(s[ni][0] - mn0), p1 = ex2f(s[ni][1] - mn0);
            float p2 = ex2f(s[ni][2] - mn1), p3 = ex2f(s[ni][3] - mn1);
            sum0 += p0 + p1; sum1 += p2 + p3;
            bf16 h0 = __float2bfloat16(p0), h1 = __float2bfloat16(p1);
            bf16 h2 = __float2bfloat16(p2), h3 = __float2bfloat16(p3);
            __nv_bfloat162 a01 = __halves2bfloat162(h0, h1);
            __nv_bfloat162 a23 = __halves2bfloat162(h2, h3);
            ph01[ni] = reinterpret_cast<uint32_t&>(a01);
            ph23[ni] = reinterpret_cast<uint32_t&>(a23);
            pl01[ni] = packf2(p0 - __bfloat162float(h0), p1 - __bfloat162float(h1));
            pl23[ni] = packf2(p2 - __bfloat162float(h2), p3 - __bfloat162float(h3));
        }
        sum0 += __shfl_xor_sync(0xffffffffu, sum0, 1);
        sum0 += __shfl_xor_sync(0xffffffffu, sum0, 2);
        sum1 += __shfl_xor_sync(0xffffffffu, sum1, 1);
        sum1 += __shfl_xor_sync(0xffffffffu, sum1, 2);
        lr0 = lr0 * cr0 + sum0;
        lr1 = lr1 * cr1 + sum1;
        #pragma unroll
        for (int ni = 0; ni < 8; ++ni) {
            o[ni][0] *= cr0; o[ni][1] *= cr0;
            o[ni][2] *= cr1; o[ni][3] *= cr1;
        }

        // ---- O += P V (bf16x3, V via ldmatrix.trans) ----
        const uint32_t vb = kb + 16384;
        #pragma unroll
        for (int kk = 0; kk < 4; ++kk) {
            uint32_t pa_h[4] = { ph01[2*kk], ph23[2*kk], ph01[2*kk+1], ph23[2*kk+1] };
            uint32_t pa_l[4] = { pl01[2*kk], pl23[2*kk], pl01[2*kk+1], pl23[2*kk+1] };
            #pragma unroll
            for (int dg = 0; dg < 4; ++dg) {
                uint32_t vd = vb + swz((kk * 16 + arow) * 128 + dg * 32 + acb);
                uint32_t vh[4], vl[4];
                ldx4t(vh, vd);
                ldx4t(vl, vd + 8192);
                mma16816(o[2*dg],   pa_h, vh);     mma16816(o[2*dg],   pa_h, vl);
                mma16816(o[2*dg],   pa_l, vh);
                mma16816(o[2*dg+1], pa_h, vh + 2); mma16816(o[2*dg+1], pa_h, vl + 2);
                mma16816(o[2*dg+1], pa_l, vh + 2);
            }
        }
    }

    // ---- epilogue ----
    const float i0 = 1.f / lr0, i1 = 1.f / lr1;
    const int b = by >> 4, h = by & 15;
    #pragma unroll
    for (int half = 0; half < 2; ++half) {
        const int l = q0 + w * 16 + g + half * 8;
        const size_t mbase = ((size_t)(b * L_ + l)) * INNER_ + h * 64;
        const float inv = half ? i1 : i0;
        #pragma unroll
        for (int ni = 0; ni < 8; ++ni) {
            int d0 = ni * 8 + tq * 2;
            store_hl(g_Oh, g_Ol, mbase + d0,
                     o[ni][half * 2] * inv, o[ni][half * 2 + 1] * inv);
        }
    }
}

// ---------------------------------------------------------------------------
extern "C" void kernel_launch(void* const* d_in, const int* in_sizes, int n_in,
                              void* d_out, int out_size)
{
    const float* x   = (const float*)d_in[0];
    const float* pe  = (const float*)d_in[1];
    const float* Wq  = (const float*)d_in[2];
    const float* Wkv = (const float*)d_in[3];
    const float* Wp  = (const float*)d_in[4];
    const float* bp  = (const float*)d_in[5];
    const float* qs  = (const float*)d_in[6];
    const float* ks  = (const float*)d_in[7];
    float* out = (float*)d_out;

    cudaFuncSetAttribute(qkv_mma,  cudaFuncAttributeMaxDynamicSharedMemorySize, 2 * GSTAGE);
    cudaFuncSetAttribute(proj_mma, cudaFuncAttributeMaxDynamicSharedMemorySize, 2 * GSTAGE);
    cudaFuncSetAttribute(attn_mma, cudaFuncAttributeMaxDynamicSharedMemorySize, ASMEM);

    bf16 *xh, *xl, *wh, *wl, *ph, *pl;
    cudaGetSymbolAddress((void**)&xh, g_xh); cudaGetSymbolAddress((void**)&xl, g_xl);
    cudaGetSymbolAddress((void**)&wh, g_Wh); cudaGetSymbolAddress((void**)&wl, g_Wl);
    cudaGetSymbolAddress((void**)&ph, g_Ph); cudaGetSymbolAddress((void**)&pl, g_Pl);

    split_kernel<<<M_ * QD_ / 4 / 256, 256>>>(x, xh, xl, M_ * QD_ / 4);
    split_kernel<<<INNER_ * QD_ / 4 / 256, 256>>>(Wq, wh, wl, INNER_ * QD_ / 4);
    split_kernel<<<2 * INNER_ * QD_ / 4 / 256, 256>>>(
        Wkv, wh + (size_t)INNER_ * QD_, wl + (size_t)INNER_ * QD_, 2 * INNER_ * QD_ / 4);
    split_kernel<<<QD_ * INNER_ / 4 / 256, 256>>>(Wp, ph, pl, QD_ * INNER_ / 4);

    qkv_mma<<<dim3(M_ / 128, NF_ / 64), 256, 2 * GSTAGE>>>(pe, qs, ks);
    attn_mma<<<dim3(L_ / 64, B_ * H_), 128, ASMEM>>>();
    proj_mma<<<dim3(M_ / 128, QD_ / 64), 256, 2 * GSTAGE>>>(bp, out);
}

// round 6
// speedup vs baseline: 4.9655x; 1.1625x over previous
#include <cuda_runtime.h>
#include <cuda_fp16.h>
#include <cstdint>

#define B_     2
#define L_     2048
#define QD_    1024
#define H_     16
#define D_     64
#define INNER_ 1024
#define M_     4096
#define NF_    3072

typedef __half fp16;

// ---------------------------------------------------------------------------
// Scratch (__device__ globals; allocation-free rule)
// ---------------------------------------------------------------------------
__device__ fp16 g_xh[M_ * QD_],  g_xl[M_ * QD_];
__device__ fp16 g_Wh[NF_ * QD_], g_Wl[NF_ * QD_];     // [Wq ; Wkv]
__device__ fp16 g_Ph[QD_ * INNER_], g_Pl[QD_ * INNER_];
__device__ fp16 g_Qh[M_ * INNER_], g_Ql[M_ * INNER_]; // [b*H+h][l][d]
__device__ fp16 g_K [M_ * INNER_];                    // single fp16
__device__ fp16 g_Vh[M_ * INNER_], g_Vl[M_ * INNER_];
__device__ fp16 g_Oh[M_ * INNER_], g_Ol[M_ * INNER_]; // [m][h*64+d]

// ---------------------------------------------------------------------------
// Baseline-PTX helpers
// ---------------------------------------------------------------------------
__device__ __forceinline__ uint32_t smem_u32(const void* p) {
    uint32_t a;
    asm("{ .reg .u64 t; cvta.to.shared.u64 t, %1; cvt.u32.u64 %0, t; }"
        : "=r"(a) : "l"(p));
    return a;
}
__device__ __forceinline__ void cpa16(uint32_t s, const void* g) {
    asm volatile("cp.async.cg.shared.global [%0], [%1], 16;" :: "r"(s), "l"(g));
}
#define CP_COMMIT() asm volatile("cp.async.commit_group;" ::: "memory")
#define CP_WAIT(n)  asm volatile("cp.async.wait_group %0;" :: "n"(n) : "memory")

__device__ __forceinline__ void ldx4(uint32_t r[4], uint32_t a) {
    asm volatile("ldmatrix.sync.aligned.m8n8.x4.shared.b16 {%0,%1,%2,%3}, [%4];"
        : "=r"(r[0]), "=r"(r[1]), "=r"(r[2]), "=r"(r[3]) : "r"(a));
}
__device__ __forceinline__ void ldx4t(uint32_t r[4], uint32_t a) {
    asm volatile("ldmatrix.sync.aligned.m8n8.x4.trans.shared.b16 {%0,%1,%2,%3}, [%4];"
        : "=r"(r[0]), "=r"(r[1]), "=r"(r[2]), "=r"(r[3]) : "r"(a));
}
__device__ __forceinline__ void mma16816(float c[4], const uint32_t a[4],
                                         const uint32_t b[2]) {
    asm volatile(
        "mma.sync.aligned.m16n8k16.row.col.f32.f16.f16.f32 "
        "{%0,%1,%2,%3}, {%4,%5,%6,%7}, {%8,%9}, {%0,%1,%2,%3};"
        : "+f"(c[0]), "+f"(c[1]), "+f"(c[2]), "+f"(c[3])
        : "r"(a[0]), "r"(a[1]), "r"(a[2]), "r"(a[3]), "r"(b[0]), "r"(b[1]));
}
__device__ __forceinline__ uint32_t swz(uint32_t o) { return o ^ ((o >> 3) & 0x70); }

__device__ __forceinline__ float ex2f(float x) {
    float y;
    asm("ex2.approx.f32 %0, %1;" : "=f"(y) : "f"(x));
    return y;
}
__device__ __forceinline__ uint32_t packh2(float x, float y) {
    __half2 h = __float22half2_rn(make_float2(x, y));
    return reinterpret_cast<uint32_t&>(h);
}
__device__ __forceinline__ void store_hl(fp16* dh, fp16* dl, size_t idx,
                                         float v0, float v1) {
    fp16 h0 = __float2half_rn(v0), h1 = __float2half_rn(v1);
    float l0 = v0 - __half2float(h0), l1 = v1 - __half2float(h1);
    __half2 hh = __halves2half2(h0, h1);
    *reinterpret_cast<uint32_t*>(dh + idx) = reinterpret_cast<uint32_t&>(hh);
    *reinterpret_cast<uint32_t*>(dl + idx) = packh2(l0, l1);
}

// ---------------------------------------------------------------------------
// fp32 -> fp16 hi/lo split
// ---------------------------------------------------------------------------
__global__ __launch_bounds__(256) void split_kernel(
    const float* __restrict__ s, fp16* __restrict__ hi, fp16* __restrict__ lo, int n4)
{
    int i = blockIdx.x * 256 + threadIdx.x;
    if (i >= n4) return;
    float4 v = reinterpret_cast<const float4*>(s)[i];
    store_hl(hi, lo, (size_t)i * 4,     v.x, v.y);
    store_hl(hi, lo, (size_t)i * 4 + 2, v.z, v.w);
}

// ---------------------------------------------------------------------------
// HMMA GEMM mainloop: C[128m x 64n] = A[m][1024] * B[n][1024]^T, fp16x3 (exact).
// 8 warps, warp tile m16 x n64. 2-stage cp.async (96KB) -> 2 CTAs/SM.
// ---------------------------------------------------------------------------
#define GSTAGE 49152
#define NCH    16

__device__ __forceinline__ void gemm_main(
    const fp16* __restrict__ Ah, const fp16* __restrict__ Al,
    const fp16* __restrict__ Bh, const fp16* __restrict__ Bl,
    int m0, int n0, char* smem, float c[8][4])
{
    const int tid = threadIdx.x;
    const int lane = tid & 31, w = tid >> 5;
    const uint32_t sb = smem_u32(smem);

    const int arow = (lane & 7) + ((lane >> 3) & 1) * 8;
    const int acb  = (lane >> 4) * 16;
    const int brow = (lane & 7) + ((lane >> 4) & 1) * 8;
    const int bcb  = ((lane >> 3) & 1) * 16;

    const fp16* Ahp = Ah + (size_t)m0 * QD_;
    const fp16* Alp = Al + (size_t)m0 * QD_;
    const fp16* Bhp = Bh + (size_t)n0 * QD_;
    const fp16* Blp = Bl + (size_t)n0 * QD_;

    auto load_stage = [&](int st, int ch) {
        uint32_t base = sb + st * GSTAGE;
        #pragma unroll
        for (int i = 0; i < 4; ++i) {
            int u = tid + i * 256;
            int row = u >> 3, s7 = u & 7;
            uint32_t so = swz(row * 128 + s7 * 16);
            cpa16(base + so,         Ahp + (size_t)row * QD_ + ch * 64 + s7 * 8);
            cpa16(base + 16384 + so, Alp + (size_t)row * QD_ + ch * 64 + s7 * 8);
        }
        #pragma unroll
        for (int i = 0; i < 2; ++i) {
            int u = tid + i * 256;
            int row = u >> 3, s7 = u & 7;
            uint32_t so = swz(row * 128 + s7 * 16);
            cpa16(base + 32768 + so, Bhp + (size_t)row * QD_ + ch * 64 + s7 * 8);
            cpa16(base + 40960 + so, Blp + (size_t)row * QD_ + ch * 64 + s7 * 8);
        }
    };

    load_stage(0, 0); CP_COMMIT();

    for (int ch = 0; ch < NCH; ++ch) {
        CP_WAIT(0);
        __syncthreads();
        if (ch + 1 < NCH) {
            load_stage((ch + 1) & 1, ch + 1);
            CP_COMMIT();
        }

        uint32_t base = sb + (ch & 1) * GSTAGE;
        #pragma unroll
        for (int ks = 0; ks < 4; ++ks) {
            uint32_t ah[4], al[4];
            uint32_t ad = base + swz((w * 16 + arow) * 128 + ks * 32 + acb);
            ldx4(ah, ad);
            ldx4(al, ad + 16384);
            #pragma unroll
            for (int ng = 0; ng < 4; ++ng) {
                uint32_t bd = base + 32768
                            + swz((ng * 16 + brow) * 128 + ks * 32 + bcb);
                uint32_t bh[4], bl[4];
                ldx4(bh, bd);
                ldx4(bl, bd + 8192);
                mma16816(c[2*ng],   ah, bh);     mma16816(c[2*ng],   ah, bl);
                mma16816(c[2*ng],   al, bh);
                mma16816(c[2*ng+1], ah, bh + 2); mma16816(c[2*ng+1], ah, bl + 2);
                mma16816(c[2*ng+1], al, bh + 2);
            }
        }
    }
}

// ---------------------------------------------------------------------------
// QKV projection GEMM + RMSNorm + RoPE -> Q hi/lo, K single, V hi/lo (fp16)
//   grid = (M_/128, NF_/64), 256 threads
// ---------------------------------------------------------------------------
__global__ __launch_bounds__(256, 2) void qkv_mma(
    const float* __restrict__ pe,
    const float* __restrict__ qsc, const float* __restrict__ ksc)
{
    extern __shared__ char smem[];
    const int m0 = blockIdx.x * 128, n0 = blockIdx.y * 64;
    float c[8][4];
    #pragma unroll
    for (int j = 0; j < 8; ++j)
        #pragma unroll
        for (int k = 0; k < 4; ++k) c[j][k] = 0.f;

    gemm_main(g_xh, g_xl, g_Wh, g_Wl, m0, n0, smem, c);

    const int tid = threadIdx.x, lane = tid & 31, w = tid >> 5;
    const int tq = lane & 3, g = lane >> 2;

    const int kind = n0 >> 10;               // 0:Q 1:K 2:V
    const int h = (n0 & 1023) >> 6;
    const float* sc = (kind == 0) ? qsc : ksc;
    const float qm = (kind == 0) ? 0.125f * 1.4426950408889634f : 1.f;

    #pragma unroll
    for (int half_ = 0; half_ < 2; ++half_) {
        const int m = m0 + w * 16 + g + half_ * 8;
        const int b = m >> 11, l = m & 2047;
        const size_t obase = ((size_t)(b * H_ + h) * L_ + l) * 64;

        if (kind == 2) {
            #pragma unroll
            for (int ni = 0; ni < 8; ++ni) {
                int d0 = ni * 8 + tq * 2;
                store_hl(g_Vh, g_Vl, obase + d0, c[ni][half_ * 2], c[ni][half_ * 2 + 1]);
            }
        } else {
            float ss = 0.f;
            #pragma unroll
            for (int ni = 0; ni < 8; ++ni) {
                float v0 = c[ni][half_ * 2], v1 = c[ni][half_ * 2 + 1];
                ss = fmaf(v0, v0, fmaf(v1, v1, ss));
            }
            ss += __shfl_xor_sync(0xffffffffu, ss, 1);
            ss += __shfl_xor_sync(0xffffffffu, ss, 2);
            const float rr = rsqrtf(ss * (1.f / 64.f) + 1e-6f);
            const float* pel = pe + (size_t)l * 128;
            #pragma unroll
            for (int ni = 0; ni < 8; ++ni) {
                int d0 = ni * 8 + tq * 2;
                float v0 = c[ni][half_ * 2]     * rr * sc[d0];
                float v1 = c[ni][half_ * 2 + 1] * rr * sc[d0 + 1];
                float4 p = *reinterpret_cast<const float4*>(pel + (d0 >> 1) * 4);
                float o0 = (p.x * v0 + p.y * v1) * qm;
                float o1 = (p.z * v0 + p.w * v1) * qm;
                if (kind == 0) store_hl(g_Qh, g_Ql, obase + d0, o0, o1);
                else *reinterpret_cast<uint32_t*>(g_K + obase + d0) = packh2(o0, o1);
            }
        }
    }
}

// ---------------------------------------------------------------------------
// Output projection GEMM + bias -> fp32 out
// ---------------------------------------------------------------------------
__global__ __launch_bounds__(256, 2) void proj_mma(
    const float* __restrict__ bp, float* __restrict__ out)
{
    extern __shared__ char smem[];
    const int m0 = blockIdx.x * 128, n0 = blockIdx.y * 64;
    float c[8][4];
    #pragma unroll
    for (int j = 0; j < 8; ++j)
        #pragma unroll
        for (int k = 0; k < 4; ++k) c[j][k] = 0.f;

    gemm_main(g_Oh, g_Ol, g_Ph, g_Pl, m0, n0, smem, c);

    const int tid = threadIdx.x, lane = tid & 31, w = tid >> 5;
    const int tq = lane & 3, g = lane >> 2;

    #pragma unroll
    for (int half_ = 0; half_ < 2; ++half_) {
        const int m = m0 + w * 16 + g + half_ * 8;
        #pragma unroll
        for (int ni = 0; ni < 8; ++ni) {
            int col = n0 + ni * 8 + tq * 2;
            float2 bv = *reinterpret_cast<const float2*>(bp + col);
            float2 o = make_float2(c[ni][half_ * 2]     + bv.x,
                                   c[ni][half_ * 2 + 1] + bv.y);
            *reinterpret_cast<float2*>(out + (size_t)m * QD_ + col) = o;
        }
    }
}

// ---------------------------------------------------------------------------
// Flash attention, fp16 HMMA, exp2-domain online softmax
//   S = (Qh+Ql)·K  (K single fp16, 2 MMAs)
//   O = P·(Vh+Vl)  (P single fp16, 2 MMAs)
//   grid = (L_/64, B_*H_), 128 threads
//   smem: Qh 8K | Ql 8K | 2 stages x (K 8K | Vh 8K | Vl 8K) = 64K -> 2 CTAs/SM
// ---------------------------------------------------------------------------
#define ASTAGE 24576
#define ASMEM  (16384 + 2 * ASTAGE)
#define NIT    32

__global__ __launch_bounds__(128, 2) void attn_mma()
{
    extern __shared__ char smem[];
    const int tid = threadIdx.x, lane = tid & 31, w = tid >> 5;
    const int by = blockIdx.y;
    const int q0 = blockIdx.x * 64;
    const uint32_t sb = smem_u32(smem);

    const fp16* Qhp = g_Qh + ((size_t)by * L_ + q0) * 64;
    const fp16* Qlp = g_Ql + ((size_t)by * L_ + q0) * 64;
    const fp16* Kp  = g_K  + (size_t)by * L_ * 64;
    const fp16* Vhp = g_Vh + (size_t)by * L_ * 64;
    const fp16* Vlp = g_Vl + (size_t)by * L_ * 64;

    const int tq = lane & 3, g = lane >> 2;
    const int arow = (lane & 7) + ((lane >> 3) & 1) * 8;
    const int acb  = (lane >> 4) * 16;
    const int brow = (lane & 7) + ((lane >> 4) & 1) * 8;
    const int bcb  = ((lane >> 3) & 1) * 16;

    auto load_kv = [&](int st, int kt) {
        uint32_t base = sb + 16384 + st * ASTAGE;
        const fp16* srcs[3] = { Kp, Vhp, Vlp };
        #pragma unroll
        for (int mtx = 0; mtx < 3; ++mtx)
            #pragma unroll
            for (int i = 0; i < 4; ++i) {
                int u = tid + i * 128;
                int row = u >> 3, s7 = u & 7;
                cpa16(base + mtx * 8192 + swz(row * 128 + s7 * 16),
                      srcs[mtx] + (size_t)(kt * 64 + row) * 64 + s7 * 8);
            }
    };

    // prologue: Q + KV stage0
    #pragma unroll
    for (int i = 0; i < 4; ++i) {
        int u = tid + i * 128;
        int row = u >> 3, s7 = u & 7;
        uint32_t so = swz(row * 128 + s7 * 16);
        cpa16(sb +        so, Qhp + (size_t)row * 64 + s7 * 8);
        cpa16(sb + 8192 + so, Qlp + (size_t)row * 64 + s7 * 8);
    }
    load_kv(0, 0); CP_COMMIT();

    float o[8][4];
    #pragma unroll
    for (int i = 0; i < 8; ++i)
        #pragma unroll
        for (int j = 0; j < 4; ++j) o[i][j] = 0.f;
    float mr0 = -1e30f, mr1 = -1e30f, lr0 = 0.f, lr1 = 0.f;
    uint32_t qhf[4][4], qlf[4][4];

    for (int it = 0; it < NIT; ++it) {
        CP_WAIT(0);
        __syncthreads();
        if (it + 1 < NIT) {
            load_kv((it + 1) & 1, it + 1);
            CP_COMMIT();
        }

        if (it == 0) {
            #pragma unroll
            for (int ks = 0; ks < 4; ++ks) {
                uint32_t ad = sb + swz((w * 16 + arow) * 128 + ks * 32 + acb);
                ldx4(qhf[ks], ad);
                ldx4(qlf[ks], ad + 8192);
            }
        }

        const uint32_t kb = sb + 16384 + (it & 1) * ASTAGE;

        // ---- S = (Qh+Ql) K^T (log2 domain) ----
        float s[8][4];
        #pragma unroll
        for (int i = 0; i < 8; ++i)
            #pragma unroll
            for (int j = 0; j < 4; ++j) s[i][j] = 0.f;

        #pragma unroll
        for (int ks = 0; ks < 4; ++ks)
            #pragma unroll
            for (int ng = 0; ng < 4; ++ng) {
                uint32_t kd = kb + swz((ng * 16 + brow) * 128 + ks * 32 + bcb);
                uint32_t kh[4];
                ldx4(kh, kd);
                mma16816(s[2*ng],   qhf[ks], kh);
                mma16816(s[2*ng],   qlf[ks], kh);
                mma16816(s[2*ng+1], qhf[ks], kh + 2);
                mma16816(s[2*ng+1], qlf[ks], kh + 2);
            }

        // ---- online softmax (exp2 domain) ----
        float mx0 = -1e30f, mx1 = -1e30f;
        #pragma unroll
        for (int ni = 0; ni < 8; ++ni) {
            mx0 = fmaxf(mx0, fmaxf(s[ni][0], s[ni][1]));
            mx1 = fmaxf(mx1, fmaxf(s[ni][2], s[ni][3]));
        }
        mx0 = fmaxf(mx0, __shfl_xor_sync(0xffffffffu, mx0, 1));
        mx0 = fmaxf(mx0, __shfl_xor_sync(0xffffffffu, mx0, 2));
        mx1 = fmaxf(mx1, __shfl_xor_sync(0xffffffffu, mx1, 1));
        mx1 = fmaxf(mx1, __shfl_xor_sync(0xffffffffu, mx1, 2));
        const float mn0 = fmaxf(mr0, mx0), mn1 = fmaxf(mr1, mx1);
        const float cr0 = ex2f(mr0 - mn0), cr1 = ex2f(mr1 - mn1);
        mr0 = mn0; mr1 = mn1;

        float sum0 = 0.f, sum1 = 0.f;
        uint32_t ph01[8], ph23[8];
        #pragma unroll
        for (int ni = 0; ni < 8; ++ni) {
            float p0 = ex2f(s[ni][0] - mn0), p1 = ex2f(s[ni][1] - mn0);
            float p2 = ex2f(s[ni][2] - mn1), p3 = ex2f(s[ni][3] - mn1);
            sum0 += p0 + p1; sum1 += p2 + p3;
            ph01[ni] = packh2(p0, p1);
            ph23[ni] = packh2(p2, p3);
        }
        sum0 += __shfl_xor_sync(0xffffffffu, sum0, 1);
        sum0 += __shfl_xor_sync(0xffffffffu, sum0, 2);
        sum1 += __shfl_xor_sync(0xffffffffu, sum1, 1);
        sum1 += __shfl_xor_sync(0xffffffffu, sum1, 2);
        lr0 = lr0 * cr0 + sum0;
        lr1 = lr1 * cr1 + sum1;
        #pragma unroll
        for (int ni = 0; ni < 8; ++ni) {
            o[ni][0] *= cr0; o[ni][1] *= cr0;
            o[ni][2] *= cr1; o[ni][3] *= cr1;
        }

        // ---- O += P (Vh+Vl) ----
        const uint32_t vb = kb + 8192;
        #pragma unroll
        for (int kk = 0; kk < 4; ++kk) {
            uint32_t pa[4] = { ph01[2*kk], ph23[2*kk], ph01[2*kk+1], ph23[2*kk+1] };
            #pragma unroll
            for (int dg = 0; dg < 4; ++dg) {
                uint32_t vd = vb + swz((kk * 16 + arow) * 128 + dg * 32 + acb);
                uint32_t vh[4], vl[4];
                ldx4t(vh, vd);
                ldx4t(vl, vd + 8192);
                mma16816(o[2*dg],   pa, vh);
                mma16816(o[2*dg],   pa, vl);
                mma16816(o[2*dg+1], pa, vh + 2);
                mma16816(o[2*dg+1], pa, vl + 2);
            }
        }
    }

    // ---- epilogue ----
    const float i0 = 1.f / lr0, i1 = 1.f / lr1;
    const int b = by >> 4, h = by & 15;
    #pragma unroll
    for (int half_ = 0; half_ < 2; ++half_) {
        const int l = q0 + w * 16 + g + half_ * 8;
        const size_t mbase = ((size_t)(b * L_ + l)) * INNER_ + h * 64;
        const float inv = half_ ? i1 : i0;
        #pragma unroll
        for (int ni = 0; ni < 8; ++ni) {
            int d0 = ni * 8 + tq * 2;
            store_hl(g_Oh, g_Ol, mbase + d0,
                     o[ni][half_ * 2] * inv, o[ni][half_ * 2 + 1] * inv);
        }
    }
}

// ---------------------------------------------------------------------------
extern "C" void kernel_launch(void* const* d_in, const int* in_sizes, int n_in,
                              void* d_out, int out_size)
{
    const float* x   = (const float*)d_in[0];
    const float* pe  = (const float*)d_in[1];
    const float* Wq  = (const float*)d_in[2];
    const float* Wkv = (const float*)d_in[3];
    const float* Wp  = (const float*)d_in[4];
    const float* bp  = (const float*)d_in[5];
    const float* qs  = (const float*)d_in[6];
    const float* ks  = (const float*)d_in[7];
    float* out = (float*)d_out;

    cudaFuncSetAttribute(qkv_mma,  cudaFuncAttributeMaxDynamicSharedMemorySize, 2 * GSTAGE);
    cudaFuncSetAttribute(proj_mma, cudaFuncAttributeMaxDynamicSharedMemorySize, 2 * GSTAGE);
    cudaFuncSetAttribute(attn_mma, cudaFuncAttributeMaxDynamicSharedMemorySize, ASMEM);

    fp16 *xh, *xl, *wh, *wl, *ph, *pl;
    cudaGetSymbolAddress((void**)&xh, g_xh); cudaGetSymbolAddress((void**)&xl, g_xl);
    cudaGetSymbolAddress((void**)&wh, g_Wh); cudaGetSymbolAddress((void**)&wl, g_Wl);
    cudaGetSymbolAddress((void**)&ph, g_Ph); cudaGetSymbolAddress((void**)&pl, g_Pl);

    split_kernel<<<M_ * QD_ / 4 / 256, 256>>>(x, xh, xl, M_ * QD_ / 4);
    split_kernel<<<INNER_ * QD_ / 4 / 256, 256>>>(Wq, wh, wl, INNER_ * QD_ / 4);
    split_kernel<<<2 * INNER_ * QD_ / 4 / 256, 256>>>(
        Wkv, wh + (size_t)INNER_ * QD_, wl + (size_t)INNER_ * QD_, 2 * INNER_ * QD_ / 4);
    split_kernel<<<QD_ * INNER_ / 4 / 256, 256>>>(Wp, ph, pl, QD_ * INNER_ / 4);

    qkv_mma<<<dim3(M_ / 128, NF_ / 64), 256, 2 * GSTAGE>>>(pe, qs, ks);
    attn_mma<<<dim3(L_ / 64, B_ * H_), 128, ASMEM>>>();
    proj_mma<<<dim3(M_ / 128, QD_ / 64), 256, 2 * GSTAGE>>>(bp, out);
}

// round 7
// speedup vs baseline: 5.3816x; 1.0838x over previous
#include <cuda_runtime.h>
#include <cuda_fp16.h>
#include <cstdint>

#define B_     2
#define L_     2048
#define QD_    1024
#define H_     16
#define D_     64
#define INNER_ 1024
#define M_     4096
#define NF_    3072

typedef __half fp16;

// ---------------------------------------------------------------------------
// Scratch (__device__ globals; allocation-free rule)
// ---------------------------------------------------------------------------
__device__ fp16 g_x [M_ * QD_];                       // single fp16 activations
__device__ fp16 g_Wh[NF_ * QD_], g_Wl[NF_ * QD_];     // [Wq ; Wkv] hi/lo
__device__ fp16 g_Ph[QD_ * INNER_], g_Pl[QD_ * INNER_];
__device__ fp16 g_Qh[M_ * INNER_], g_Ql[M_ * INNER_]; // [b*H+h][l][d]
__device__ fp16 g_K [M_ * INNER_];                    // single fp16
__device__ fp16 g_Vh[M_ * INNER_], g_Vl[M_ * INNER_];
__device__ fp16 g_Oh[M_ * INNER_], g_Ol[M_ * INNER_]; // [m][h*64+d]

// ---------------------------------------------------------------------------
// Baseline-PTX helpers
// ---------------------------------------------------------------------------
__device__ __forceinline__ uint32_t smem_u32(const void* p) {
    uint32_t a;
    asm("{ .reg .u64 t; cvta.to.shared.u64 t, %1; cvt.u32.u64 %0, t; }"
        : "=r"(a) : "l"(p));
    return a;
}
__device__ __forceinline__ void cpa16(uint32_t s, const void* g) {
    asm volatile("cp.async.cg.shared.global [%0], [%1], 16;" :: "r"(s), "l"(g));
}
#define CP_COMMIT() asm volatile("cp.async.commit_group;" ::: "memory")
#define CP_WAIT(n)  asm volatile("cp.async.wait_group %0;" :: "n"(n) : "memory")

__device__ __forceinline__ void ldx4(uint32_t r[4], uint32_t a) {
    asm volatile("ldmatrix.sync.aligned.m8n8.x4.shared.b16 {%0,%1,%2,%3}, [%4];"
        : "=r"(r[0]), "=r"(r[1]), "=r"(r[2]), "=r"(r[3]) : "r"(a));
}
__device__ __forceinline__ void ldx4t(uint32_t r[4], uint32_t a) {
    asm volatile("ldmatrix.sync.aligned.m8n8.x4.trans.shared.b16 {%0,%1,%2,%3}, [%4];"
        : "=r"(r[0]), "=r"(r[1]), "=r"(r[2]), "=r"(r[3]) : "r"(a));
}
__device__ __forceinline__ void mma16816(float c[4], const uint32_t a[4],
                                         const uint32_t b[2]) {
    asm volatile(
        "mma.sync.aligned.m16n8k16.row.col.f32.f16.f16.f32 "
        "{%0,%1,%2,%3}, {%4,%5,%6,%7}, {%8,%9}, {%0,%1,%2,%3};"
        : "+f"(c[0]), "+f"(c[1]), "+f"(c[2]), "+f"(c[3])
        : "r"(a[0]), "r"(a[1]), "r"(a[2]), "r"(a[3]), "r"(b[0]), "r"(b[1]));
}
__device__ __forceinline__ uint32_t swz(uint32_t o) { return o ^ ((o >> 3) & 0x70); }

__device__ __forceinline__ float ex2f(float x) {
    float y;
    asm("ex2.approx.f32 %0, %1;" : "=f"(y) : "f"(x));
    return y;
}
__device__ __forceinline__ uint32_t packh2(float x, float y) {
    __half2 h = __float22half2_rn(make_float2(x, y));
    return reinterpret_cast<uint32_t&>(h);
}
__device__ __forceinline__ float2 unpackh2(uint32_t u) {
    return __half22float2(reinterpret_cast<__half2&>(u));
}
__device__ __forceinline__ void store_hl(fp16* dh, fp16* dl, size_t idx,
                                         float v0, float v1) {
    fp16 h0 = __float2half_rn(v0), h1 = __float2half_rn(v1);
    float l0 = v0 - __half2float(h0), l1 = v1 - __half2float(h1);
    __half2 hh = __halves2half2(h0, h1);
    *reinterpret_cast<uint32_t*>(dh + idx) = reinterpret_cast<uint32_t&>(hh);
    *reinterpret_cast<uint32_t*>(dl + idx) = packh2(l0, l1);
}

// ---------------------------------------------------------------------------
// fp32 -> fp16 hi/lo split ; fp32 -> fp16 convert
// ---------------------------------------------------------------------------
__global__ __launch_bounds__(256) void split_kernel(
    const float* __restrict__ s, fp16* __restrict__ hi, fp16* __restrict__ lo, int n4)
{
    int i = blockIdx.x * 256 + threadIdx.x;
    if (i >= n4) return;
    float4 v = reinterpret_cast<const float4*>(s)[i];
    store_hl(hi, lo, (size_t)i * 4,     v.x, v.y);
    store_hl(hi, lo, (size_t)i * 4 + 2, v.z, v.w);
}

__global__ __launch_bounds__(256) void cvt_kernel(
    const float* __restrict__ s, fp16* __restrict__ d, int n4)
{
    int i = blockIdx.x * 256 + threadIdx.x;
    if (i >= n4) return;
    float4 v = reinterpret_cast<const float4*>(s)[i];
    uint2 o = make_uint2(packh2(v.x, v.y), packh2(v.z, v.w));
    *reinterpret_cast<uint2*>(d + (size_t)i * 4) = o;
}

// ---------------------------------------------------------------------------
// GEMM mainloop A-single x B-dual: C[128m x 64n] = A * (Bh+Bl)^T  (2 MMAs)
// Stage: A 16K | Bh 8K | Bl 8K = 32K; 2 stages = 64K -> 2 CTAs/SM
// ---------------------------------------------------------------------------
#define QSTAGE 32768
#define NCH    16

__device__ __forceinline__ void gemm_a1b2(
    const fp16* __restrict__ A,
    const fp16* __restrict__ Bh, const fp16* __restrict__ Bl,
    int m0, int n0, char* smem, float c[8][4])
{
    const int tid = threadIdx.x;
    const int lane = tid & 31, w = tid >> 5;
    const uint32_t sb = smem_u32(smem);

    const int arow = (lane & 7) + ((lane >> 3) & 1) * 8;
    const int acb  = (lane >> 4) * 16;
    const int brow = (lane & 7) + ((lane >> 4) & 1) * 8;
    const int bcb  = ((lane >> 3) & 1) * 16;

    const fp16* Ap  = A  + (size_t)m0 * QD_;
    const fp16* Bhp = Bh + (size_t)n0 * QD_;
    const fp16* Blp = Bl + (size_t)n0 * QD_;

    auto load_stage = [&](int st, int ch) {
        uint32_t base = sb + st * QSTAGE;
        #pragma unroll
        for (int i = 0; i < 4; ++i) {
            int u = tid + i * 256;
            int row = u >> 3, s7 = u & 7;
            cpa16(base + swz(row * 128 + s7 * 16),
                  Ap + (size_t)row * QD_ + ch * 64 + s7 * 8);
        }
        #pragma unroll
        for (int i = 0; i < 2; ++i) {
            int u = tid + i * 256;
            int row = u >> 3, s7 = u & 7;
            uint32_t so = swz(row * 128 + s7 * 16);
            cpa16(base + 16384 + so, Bhp + (size_t)row * QD_ + ch * 64 + s7 * 8);
            cpa16(base + 24576 + so, Blp + (size_t)row * QD_ + ch * 64 + s7 * 8);
        }
    };

    load_stage(0, 0); CP_COMMIT();

    for (int ch = 0; ch < NCH; ++ch) {
        CP_WAIT(0);
        __syncthreads();
        if (ch + 1 < NCH) {
            load_stage((ch + 1) & 1, ch + 1);
            CP_COMMIT();
        }

        uint32_t base = sb + (ch & 1) * QSTAGE;
        #pragma unroll
        for (int ks = 0; ks < 4; ++ks) {
            uint32_t a[4];
            ldx4(a, base + swz((w * 16 + arow) * 128 + ks * 32 + acb));
            #pragma unroll
            for (int ng = 0; ng < 4; ++ng) {
                uint32_t bd = base + 16384
                            + swz((ng * 16 + brow) * 128 + ks * 32 + bcb);
                uint32_t bh[4], bl[4];
                ldx4(bh, bd);
                ldx4(bl, bd + 8192);
                mma16816(c[2*ng],   a, bh);     mma16816(c[2*ng],   a, bl);
                mma16816(c[2*ng+1], a, bh + 2); mma16816(c[2*ng+1], a, bl + 2);
            }
        }
    }
}

// ---------------------------------------------------------------------------
// GEMM mainloop A-dual x B-dual (fp16x3, exact): used by proj
// Stage: Ah 16K | Al 16K | Bh 8K | Bl 8K = 48K; 2 stages = 96K -> 2 CTAs/SM
// ---------------------------------------------------------------------------
#define GSTAGE 49152

__device__ __forceinline__ void gemm_a2b2(
    const fp16* __restrict__ Ah, const fp16* __restrict__ Al,
    const fp16* __restrict__ Bh, const fp16* __restrict__ Bl,
    int m0, int n0, char* smem, float c[8][4])
{
    const int tid = threadIdx.x;
    const int lane = tid & 31, w = tid >> 5;
    const uint32_t sb = smem_u32(smem);

    const int arow = (lane & 7) + ((lane >> 3) & 1) * 8;
    const int acb  = (lane >> 4) * 16;
    const int brow = (lane & 7) + ((lane >> 4) & 1) * 8;
    const int bcb  = ((lane >> 3) & 1) * 16;

    const fp16* Ahp = Ah + (size_t)m0 * QD_;
    const fp16* Alp = Al + (size_t)m0 * QD_;
    const fp16* Bhp = Bh + (size_t)n0 * QD_;
    const fp16* Blp = Bl + (size_t)n0 * QD_;

    auto load_stage = [&](int st, int ch) {
        uint32_t base = sb + st * GSTAGE;
        #pragma unroll
        for (int i = 0; i < 4; ++i) {
            int u = tid + i * 256;
            int row = u >> 3, s7 = u & 7;
            uint32_t so = swz(row * 128 + s7 * 16);
            cpa16(base + so,         Ahp + (size_t)row * QD_ + ch * 64 + s7 * 8);
            cpa16(base + 16384 + so, Alp + (size_t)row * QD_ + ch * 64 + s7 * 8);
        }
        #pragma unroll
        for (int i = 0; i < 2; ++i) {
            int u = tid + i * 256;
            int row = u >> 3, s7 = u & 7;
            uint32_t so = swz(row * 128 + s7 * 16);
            cpa16(base + 32768 + so, Bhp + (size_t)row * QD_ + ch * 64 + s7 * 8);
            cpa16(base + 40960 + so, Blp + (size_t)row * QD_ + ch * 64 + s7 * 8);
        }
    };

    load_stage(0, 0); CP_COMMIT();

    for (int ch = 0; ch < NCH; ++ch) {
        CP_WAIT(0);
        __syncthreads();
        if (ch + 1 < NCH) {
            load_stage((ch + 1) & 1, ch + 1);
            CP_COMMIT();
        }

        uint32_t base = sb + (ch & 1) * GSTAGE;
        #pragma unroll
        for (int ks = 0; ks < 4; ++ks) {
            uint32_t ah[4], al[4];
            uint32_t ad = base + swz((w * 16 + arow) * 128 + ks * 32 + acb);
            ldx4(ah, ad);
            ldx4(al, ad + 16384);
            #pragma unroll
            for (int ng = 0; ng < 4; ++ng) {
                uint32_t bd = base + 32768
                            + swz((ng * 16 + brow) * 128 + ks * 32 + bcb);
                uint32_t bh[4], bl[4];
                ldx4(bh, bd);
                ldx4(bl, bd + 8192);
                mma16816(c[2*ng],   ah, bh);     mma16816(c[2*ng],   ah, bl);
                mma16816(c[2*ng],   al, bh);
                mma16816(c[2*ng+1], ah, bh + 2); mma16816(c[2*ng+1], ah, bl + 2);
                mma16816(c[2*ng+1], al, bh + 2);
            }
        }
    }
}

// ---------------------------------------------------------------------------
// QKV projection GEMM (x single * W hi/lo) + RMSNorm + RoPE
//   grid = (M_/128, NF_/64), 256 threads
// ---------------------------------------------------------------------------
__global__ __launch_bounds__(256, 2) void qkv_mma(
    const float* __restrict__ pe,
    const float* __restrict__ qsc, const float* __restrict__ ksc)
{
    extern __shared__ char smem[];
    const int m0 = blockIdx.x * 128, n0 = blockIdx.y * 64;
    float c[8][4];
    #pragma unroll
    for (int j = 0; j < 8; ++j)
        #pragma unroll
        for (int k = 0; k < 4; ++k) c[j][k] = 0.f;

    gemm_a1b2(g_x, g_Wh, g_Wl, m0, n0, smem, c);

    const int tid = threadIdx.x, lane = tid & 31, w = tid >> 5;
    const int tq = lane & 3, g = lane >> 2;

    const int kind = n0 >> 10;               // 0:Q 1:K 2:V
    const int h = (n0 & 1023) >> 6;
    const float* sc = (kind == 0) ? qsc : ksc;
    const float qm = (kind == 0) ? 0.125f * 1.4426950408889634f : 1.f;

    #pragma unroll
    for (int half_ = 0; half_ < 2; ++half_) {
        const int m = m0 + w * 16 + g + half_ * 8;
        const int b = m >> 11, l = m & 2047;
        const size_t obase = ((size_t)(b * H_ + h) * L_ + l) * 64;

        if (kind == 2) {
            #pragma unroll
            for (int ni = 0; ni < 8; ++ni) {
                int d0 = ni * 8 + tq * 2;
                store_hl(g_Vh, g_Vl, obase + d0, c[ni][half_ * 2], c[ni][half_ * 2 + 1]);
            }
        } else {
            float ss = 0.f;
            #pragma unroll
            for (int ni = 0; ni < 8; ++ni) {
                float v0 = c[ni][half_ * 2], v1 = c[ni][half_ * 2 + 1];
                ss = fmaf(v0, v0, fmaf(v1, v1, ss));
            }
            ss += __shfl_xor_sync(0xffffffffu, ss, 1);
            ss += __shfl_xor_sync(0xffffffffu, ss, 2);
            const float rr = rsqrtf(ss * (1.f / 64.f) + 1e-6f);
            const float* pel = pe + (size_t)l * 128;
            #pragma unroll
            for (int ni = 0; ni < 8; ++ni) {
                int d0 = ni * 8 + tq * 2;
                float v0 = c[ni][half_ * 2]     * rr * sc[d0];
                float v1 = c[ni][half_ * 2 + 1] * rr * sc[d0 + 1];
                float4 p = *reinterpret_cast<const float4*>(pel + (d0 >> 1) * 4);
                float o0 = (p.x * v0 + p.y * v1) * qm;
                float o1 = (p.z * v0 + p.w * v1) * qm;
                if (kind == 0) store_hl(g_Qh, g_Ql, obase + d0, o0, o1);
                else *reinterpret_cast<uint32_t*>(g_K + obase + d0) = packh2(o0, o1);
            }
        }
    }
}

// ---------------------------------------------------------------------------
// Output projection GEMM (O hi/lo * Wp hi/lo, exact) + bias
// ---------------------------------------------------------------------------
__global__ __launch_bounds__(256, 2) void proj_mma(
    const float* __restrict__ bp, float* __restrict__ out)
{
    extern __shared__ char smem[];
    const int m0 = blockIdx.x * 128, n0 = blockIdx.y * 64;
    float c[8][4];
    #pragma unroll
    for (int j = 0; j < 8; ++j)
        #pragma unroll
        for (int k = 0; k < 4; ++k) c[j][k] = 0.f;

    gemm_a2b2(g_Oh, g_Ol, g_Ph, g_Pl, m0, n0, smem, c);

    const int tid = threadIdx.x, lane = tid & 31, w = tid >> 5;
    const int tq = lane & 3, g = lane >> 2;

    #pragma unroll
    for (int half_ = 0; half_ < 2; ++half_) {
        const int m = m0 + w * 16 + g + half_ * 8;
        #pragma unroll
        for (int ni = 0; ni < 8; ++ni) {
            int col = n0 + ni * 8 + tq * 2;
            float2 bv = *reinterpret_cast<const float2*>(bp + col);
            float2 o = make_float2(c[ni][half_ * 2]     + bv.x,
                                   c[ni][half_ * 2 + 1] + bv.y);
            *reinterpret_cast<float2*>(out + (size_t)m * QD_ + col) = o;
        }
    }
}

// ---------------------------------------------------------------------------
// Flash attention, fp16 HMMA, exp2-domain online softmax
//   S = (Qh+Ql)·K ; O = P̂·(Vh+Vl) with CONSISTENT quantized-sum normalization
//   grid = (L_/64, B_*H_), 128 threads; 2 CTAs/SM
// ---------------------------------------------------------------------------
#define ASTAGE 24576
#define ASMEM  (16384 + 2 * ASTAGE)
#define NIT    32

__global__ __launch_bounds__(128, 2) void attn_mma()
{
    extern __shared__ char smem[];
    const int tid = threadIdx.x, lane = tid & 31, w = tid >> 5;
    const int by = blockIdx.y;
    const int q0 = blockIdx.x * 64;
    const uint32_t sb = smem_u32(smem);

    const fp16* Qhp = g_Qh + ((size_t)by * L_ + q0) * 64;
    const fp16* Qlp = g_Ql + ((size_t)by * L_ + q0) * 64;
    const fp16* Kp  = g_K  + (size_t)by * L_ * 64;
    const fp16* Vhp = g_Vh + (size_t)by * L_ * 64;
    const fp16* Vlp = g_Vl + (size_t)by * L_ * 64;

    const int tq = lane & 3, g = lane >> 2;
    const int arow = (lane & 7) + ((lane >> 3) & 1) * 8;
    const int acb  = (lane >> 4) * 16;
    const int brow = (lane & 7) + ((lane >> 4) & 1) * 8;
    const int bcb  = ((lane >> 3) & 1) * 16;

    auto load_kv = [&](int st, int kt) {
        uint32_t base = sb + 16384 + st * ASTAGE;
        const fp16* srcs[3] = { Kp, Vhp, Vlp };
        #pragma unroll
        for (int mtx = 0; mtx < 3; ++mtx)
            #pragma unroll
            for (int i = 0; i < 4; ++i) {
                int u = tid + i * 128;
                int row = u >> 3, s7 = u & 7;
                cpa16(base + mtx * 8192 + swz(row * 128 + s7 * 16),
                      srcs[mtx] + (size_t)(kt * 64 + row) * 64 + s7 * 8);
            }
    };

    #pragma unroll
    for (int i = 0; i < 4; ++i) {
        int u = tid + i * 128;
        int row = u >> 3, s7 = u & 7;
        uint32_t so = swz(row * 128 + s7 * 16);
        cpa16(sb +        so, Qhp + (size_t)row * 64 + s7 * 8);
        cpa16(sb + 8192 + so, Qlp + (size_t)row * 64 + s7 * 8);
    }
    load_kv(0, 0); CP_COMMIT();

    float o[8][4];
    #pragma unroll
    for (int i = 0; i < 8; ++i)
        #pragma unroll
        for (int j = 0; j < 4; ++j) o[i][j] = 0.f;
    float mr0 = -1e30f, mr1 = -1e30f, lr0 = 0.f, lr1 = 0.f;
    uint32_t qhf[4][4], qlf[4][4];

    for (int it = 0; it < NIT; ++it) {
        CP_WAIT(0);
        __syncthreads();
        if (it + 1 < NIT) {
            load_kv((it + 1) & 1, it + 1);
            CP_COMMIT();
        }

        if (it == 0) {
            #pragma unroll
            for (int ks = 0; ks < 4; ++ks) {
                uint32_t ad = sb + swz((w * 16 + arow) * 128 + ks * 32 + acb);
                ldx4(qhf[ks], ad);
                ldx4(qlf[ks], ad + 8192);
            }
        }

        const uint32_t kb = sb + 16384 + (it & 1) * ASTAGE;

        // ---- S = (Qh+Ql) K^T (log2 domain) ----
        float s[8][4];
        #pragma unroll
        for (int i = 0; i < 8; ++i)
            #pragma unroll
            for (int j = 0; j < 4; ++j) s[i][j] = 0.f;

        #pragma unroll
        for (int ks = 0; ks < 4; ++ks)
            #pragma unroll
            for (int ng = 0; ng < 4; ++ng) {
                uint32_t kd = kb + swz((ng * 16 + brow) * 128 + ks * 32 + bcb);
                uint32_t kh[4];
                ldx4(kh, kd);
                mma16816(s[2*ng],   qhf[ks], kh);
                mma16816(s[2*ng],   qlf[ks], kh);
                mma16816(s[2*ng+1], qhf[ks], kh + 2);
                mma16816(s[2*ng+1], qlf[ks], kh + 2);
            }

        // ---- online softmax (exp2 domain, consistent quantized sums) ----
        float mx0 = -1e30f, mx1 = -1e30f;
        #pragma unroll
        for (int ni = 0; ni < 8; ++ni) {
            mx0 = fmaxf(mx0, fmaxf(s[ni][0], s[ni][1]));
            mx1 = fmaxf(mx1, fmaxf(s[ni][2], s[ni][3]));
        }
        mx0 = fmaxf(mx0, __shfl_xor_sync(0xffffffffu, mx0, 1));
        mx0 = fmaxf(mx0, __shfl_xor_sync(0xffffffffu, mx0, 2));
        mx1 = fmaxf(mx1, __shfl_xor_sync(0xffffffffu, mx1, 1));
        mx1 = fmaxf(mx1, __shfl_xor_sync(0xffffffffu, mx1, 2));
        const float mn0 = fmaxf(mr0, mx0), mn1 = fmaxf(mr1, mx1);
        const float cr0 = ex2f(mr0 - mn0), cr1 = ex2f(mr1 - mn1);
        mr0 = mn0; mr1 = mn1;

        float sum0 = 0.f, sum1 = 0.f;   // sums of QUANTIZED p (match MMA weights)
        uint32_t ph01[8], ph23[8];
        #pragma unroll
        for (int ni = 0; ni < 8; ++ni) {
            float p0 = ex2f(s[ni][0] - mn0), p1 = ex2f(s[ni][1] - mn0);
            float p2 = ex2f(s[ni][2] - mn1), p3 = ex2f(s[ni][3] - mn1);
            ph01[ni] = packh2(p0, p1);
            ph23[ni] = packh2(p2, p3);
            float2 q01 = unpackh2(ph01[ni]);
            float2 q23 = unpackh2(ph23[ni]);
            sum0 += q01.x + q01.y;
            sum1 += q23.x + q23.y;
        }
        sum0 += __shfl_xor_sync(0xffffffffu, sum0, 1);
        sum0 += __shfl_xor_sync(0xffffffffu, sum0, 2);
        sum1 += __shfl_xor_sync(0xffffffffu, sum1, 1);
        sum1 += __shfl_xor_sync(0xffffffffu, sum1, 2);
        lr0 = lr0 * cr0 + sum0;
        lr1 = lr1 * cr1 + sum1;
        #pragma unroll
        for (int ni = 0; ni < 8; ++ni) {
            o[ni][0] *= cr0; o[ni][1] *= cr0;
            o[ni][2] *= cr1; o[ni][3] *= cr1;
        }

        // ---- O += P̂ (Vh+Vl) ----
        const uint32_t vb = kb + 8192;
        #pragma unroll
        for (int kk = 0; kk < 4; ++kk) {
            uint32_t pa[4] = { ph01[2*kk], ph23[2*kk], ph01[2*kk+1], ph23[2*kk+1] };
            #pragma unroll
            for (int dg = 0; dg < 4; ++dg) {
                uint32_t vd = vb + swz((kk * 16 + arow) * 128 + dg * 32 + acb);
                uint32_t vh[4], vl[4];
                ldx4t(vh, vd);
                ldx4t(vl, vd + 8192);
                mma16816(o[2*dg],   pa, vh);
                mma16816(o[2*dg],   pa, vl);
                mma16816(o[2*dg+1], pa, vh + 2);
                mma16816(o[2*dg+1], pa, vl + 2);
            }
        }
    }

    // ---- epilogue ----
    const float i0 = 1.f / lr0, i1 = 1.f / lr1;
    const int b = by >> 4, h = by & 15;
    #pragma unroll
    for (int half_ = 0; half_ < 2; ++half_) {
        const int l = q0 + w * 16 + g + half_ * 8;
        const size_t mbase = ((size_t)(b * L_ + l)) * INNER_ + h * 64;
        const float inv = half_ ? i1 : i0;
        #pragma unroll
        for (int ni = 0; ni < 8; ++ni) {
            int d0 = ni * 8 + tq * 2;
            store_hl(g_Oh, g_Ol, mbase + d0,
                     o[ni][half_ * 2] * inv, o[ni][half_ * 2 + 1] * inv);
        }
    }
}

// ---------------------------------------------------------------------------
extern "C" void kernel_launch(void* const* d_in, const int* in_sizes, int n_in,
                              void* d_out, int out_size)
{
    const float* x   = (const float*)d_in[0];
    const float* pe  = (const float*)d_in[1];
    const float* Wq  = (const float*)d_in[2];
    const float* Wkv = (const float*)d_in[3];
    const float* Wp  = (const float*)d_in[4];
    const float* bp  = (const float*)d_in[5];
    const float* qs  = (const float*)d_in[6];
    const float* ks  = (const float*)d_in[7];
    float* out = (float*)d_out;

    cudaFuncSetAttribute(qkv_mma,  cudaFuncAttributeMaxDynamicSharedMemorySize, 2 * QSTAGE);
    cudaFuncSetAttribute(proj_mma, cudaFuncAttributeMaxDynamicSharedMemorySize, 2 * GSTAGE);
    cudaFuncSetAttribute(attn_mma, cudaFuncAttributeMaxDynamicSharedMemorySize, ASMEM);

    fp16 *xp, *wh, *wl, *ph, *pl;
    cudaGetSymbolAddress((void**)&xp, g_x);
    cudaGetSymbolAddress((void**)&wh, g_Wh); cudaGetSymbolAddress((void**)&wl, g_Wl);
    cudaGetSymbolAddress((void**)&ph, g_Ph); cudaGetSymbolAddress((void**)&pl, g_Pl);

    cvt_kernel<<<M_ * QD_ / 4 / 256, 256>>>(x, xp, M_ * QD_ / 4);
    split_kernel<<<INNER_ * QD_ / 4 / 256, 256>>>(Wq, wh, wl, INNER_ * QD_ / 4);
    split_kernel<<<2 * INNER_ * QD_ / 4 / 256, 256>>>(
        Wkv, wh + (size_t)INNER_ * QD_, wl + (size_t)INNER_ * QD_, 2 * INNER_ * QD_ / 4);
    split_kernel<<<QD_ * INNER_ / 4 / 256, 256>>>(Wp, ph, pl, QD_ * INNER_ / 4);

    qkv_mma<<<dim3(M_ / 128, NF_ / 64), 256, 2 * QSTAGE>>>(pe, qs, ks);
    attn_mma<<<dim3(L_ / 64, B_ * H_), 128, ASMEM>>>();
    proj_mma<<<dim3(M_ / 128, QD_ / 64), 256, 2 * GSTAGE>>>(bp, out);
}